// round 10
// baseline (speedup 1.0000x reference)
#include <cuda_runtime.h>
#include <cuda_fp16.h>
#include <math.h>
#include <stdint.h>

// ---------------------------------------------------------------------------
// Problem constants
// ---------------------------------------------------------------------------
#define BB   512
#define NI_  36
#define NT_  64
#define DI_  2048
#define DT_  768
#define GG   1024
#define HH   512
#define CC   32
#define DD   4
#define LL   2
#define NHH  8
#define DHH  64

constexpr size_t UU = (size_t)BB * NT_ * HH;   // 16.78M elements, the unit tile

// ---------------------------------------------------------------------------
// fp32 scratch
// ---------------------------------------------------------------------------
constexpr size_t O_IMGN  = 0;
constexpr size_t O_TXTN  = O_IMGN  + (size_t)BB*NI_*HH;
constexpr size_t O_IMGC  = O_TXTN  + UU;
constexpr size_t O_TXTC  = O_IMGC  + (size_t)BB*CC*HH;
constexpr size_t O_TMPA  = O_TXTC  + (size_t)BB*CC*HH;   // fp32 tmp lane A
constexpr size_t O_TMPB  = O_TMPA  + UU;                 // fp32 tmp lane B
constexpr size_t O_C2A   = O_TMPB  + UU;
constexpr size_t O_C2B   = O_C2A   + (size_t)BB*NI_*HH;
constexpr size_t O_IMGNF = O_C2B   + (size_t)BB*NI_*HH;
constexpr size_t O_TXTNF = O_IMGNF + (size_t)BB*NI_*HH;
constexpr size_t O_P2    = O_TXTNF + UU;
constexpr size_t O_P3    = O_P2    + (size_t)BB*NI_*HH;
constexpr size_t O_QI    = O_P3    + UU;
constexpr size_t O_QT    = O_QI    + (size_t)BB*HH;
constexpr size_t O_ALLI  = O_QT    + (size_t)BB*HH;
constexpr size_t O_ALLT  = O_ALLI  + (size_t)BB*40*HH;
constexpr size_t O_SIM   = O_ALLT  + (size_t)BB*68*HH;
constexpr size_t O_MU    = O_SIM   + (size_t)BB*40*68;
constexpr size_t O_MV    = O_MU    + (size_t)BB*40;
constexpr size_t O_CN0   = O_MV    + (size_t)BB*68;
constexpr size_t O_CN1   = O_CN0   + (size_t)CC*HH;
constexpr size_t O_DB0   = O_CN1   + (size_t)CC*HH;
constexpr size_t O_DB1   = O_DB0   + (size_t)DD*HH;
constexpr size_t O_DBP   = O_DB1   + (size_t)DD*HH;
constexpr size_t O_DBP2  = O_DBP   + (size_t)DD*HH;
constexpr size_t TOTAL_F = O_DBP2  + (size_t)DD*HH;
__device__ __align__(256) float g_buf[TOTAL_F];

// ---------------------------------------------------------------------------
// fp16 activation scratch (lane-private xlayer blocks + shared tail blocks)
// ---------------------------------------------------------------------------
constexpr size_t LANE_H   = 10 * UU;           // TGT+SRC+AO+HID(4U)+Q+KV(2U)
constexpr size_t HL_TGT   = 0;
constexpr size_t HL_SRC   = UU;
constexpr size_t HL_AO    = 2 * UU;
constexpr size_t HL_HID   = 3 * UU;
constexpr size_t HL_Q     = 7 * UU;
constexpr size_t HL_KV    = 8 * UU;            // 2U
constexpr size_t HB_LANE  = 0;
constexpr size_t HB_INI   = HB_LANE + 2 * LANE_H;
constexpr size_t HB_INT   = HB_INI  + (size_t)BB*NI_*DI_;
constexpr size_t HB_GI    = HB_INT  + (size_t)BB*NT_*DT_;
constexpr size_t HB_GT    = HB_GI   + (size_t)BB*GG;
constexpr size_t HB_IMGNF = HB_GT   + (size_t)BB*GG;
constexpr size_t HB_TXTNF = HB_IMGNF + (size_t)BB*NI_*HH;
constexpr size_t TOTAL_H  = HB_TXTNF + UU;
__device__ __align__(256) __half g_hbuf[TOTAL_H];

// ---------------------------------------------------------------------------
// fp16 weight scratch (single term, weights pre-scaled by 64)
// ---------------------------------------------------------------------------
constexpr size_t SZ_IMGIN = (size_t)HH*DI_;
constexpr size_t SZ_TXTIN = (size_t)HH*DT_;
constexpr size_t SZ_AIN   = (size_t)8*3*HH*HH;
constexpr size_t SZ_AOUT  = (size_t)8*HH*HH;
constexpr size_t SZ_FF1   = (size_t)8*4*HH*HH;
constexpr size_t SZ_FF2   = (size_t)8*4*HH*HH;
constexpr size_t SZ_PROJ  = (size_t)6*HH*HH;
constexpr size_t SZ_QG    = (size_t)2*HH*GG;
constexpr size_t WO_IMGIN = 0;
constexpr size_t WO_TXTIN = WO_IMGIN + SZ_IMGIN;
constexpr size_t WO_AIN   = WO_TXTIN + SZ_TXTIN;
constexpr size_t WO_AOUT  = WO_AIN   + SZ_AIN;
constexpr size_t WO_FF1   = WO_AOUT  + SZ_AOUT;
constexpr size_t WO_FF2   = WO_FF1   + SZ_FF1;
constexpr size_t WO_PROJ  = WO_FF2   + SZ_FF2;
constexpr size_t WO_QG    = WO_PROJ  + SZ_PROJ;
constexpr size_t TOTAL_W  = WO_QG    + SZ_QG;
__device__ __align__(256) __half g_wbuf[TOTAL_W];

#define WSCALE   64.0f
#define WUNSCALE 0.015625f

// ---------------------------------------------------------------------------
// PTX helpers (sm_80-era only)
// ---------------------------------------------------------------------------
__device__ __forceinline__ uint32_t s2u(const void* p) {
    uint32_t a;
    asm("{ .reg .u64 t; cvta.to.shared.u64 t, %1; cvt.u32.u64 %0, t; }"
        : "=r"(a) : "l"(p));
    return a;
}
__device__ __forceinline__ void ldsm_x4(uint32_t* r, uint32_t addr) {
    asm volatile("ldmatrix.sync.aligned.m8n8.x4.shared.b16 {%0,%1,%2,%3}, [%4];"
                 : "=r"(r[0]), "=r"(r[1]), "=r"(r[2]), "=r"(r[3]) : "r"(addr));
}
__device__ __forceinline__ void ldsm_x2(uint32_t* r, uint32_t addr) {
    asm volatile("ldmatrix.sync.aligned.m8n8.x2.shared.b16 {%0,%1}, [%2];"
                 : "=r"(r[0]), "=r"(r[1]) : "r"(addr));
}
__device__ __forceinline__ void mma_f16(float* c, const uint32_t* a, const uint32_t* b) {
    asm volatile(
        "mma.sync.aligned.m16n8k16.row.col.f32.f16.f16.f32 "
        "{%0,%1,%2,%3}, {%4,%5,%6,%7}, {%8,%9}, {%0,%1,%2,%3};"
        : "+f"(c[0]), "+f"(c[1]), "+f"(c[2]), "+f"(c[3])
        : "r"(a[0]), "r"(a[1]), "r"(a[2]), "r"(a[3]), "r"(b[0]), "r"(b[1]));
}
__device__ __forceinline__ float gelu_f(float x) {
    return 0.5f * x * (1.0f + erff(x * 0.7071067811865476f));
}

// ---------------------------------------------------------------------------
// Conversion kernels
// ---------------------------------------------------------------------------
__global__ void wconv_kernel(const float* __restrict__ w, __half* __restrict__ hi,
                             size_t n4)
{
    for (size_t i = blockIdx.x * (size_t)blockDim.x + threadIdx.x; i < n4;
         i += (size_t)gridDim.x * blockDim.x) {
        float4 f = reinterpret_cast<const float4*>(w)[i];
        __half2 H01 = __floats2half2_rn(f.x * WSCALE, f.y * WSCALE);
        __half2 H23 = __floats2half2_rn(f.z * WSCALE, f.w * WSCALE);
        uint2 Hv;
        Hv.x = *reinterpret_cast<uint32_t*>(&H01);
        Hv.y = *reinterpret_cast<uint32_t*>(&H23);
        reinterpret_cast<uint2*>(hi)[i] = Hv;
    }
}

__global__ void aconv_kernel(const float* __restrict__ x, __half* __restrict__ y, size_t n4)
{
    for (size_t i = blockIdx.x * (size_t)blockDim.x + threadIdx.x; i < n4;
         i += (size_t)gridDim.x * blockDim.x) {
        float4 f = reinterpret_cast<const float4*>(x)[i];
        __half2 a = __floats2half2_rn(f.x, f.y);
        __half2 b = __floats2half2_rn(f.z, f.w);
        uint2 o;
        o.x = *reinterpret_cast<uint32_t*>(&a);
        o.y = *reinterpret_cast<uint32_t*>(&b);
        reinterpret_cast<uint2*>(y)[i] = o;
    }
}

// ---------------------------------------------------------------------------
// fp16 tensor-core GEMM (single term): C = A @ W^T * 2^-6 + bias (+res/gelu)
// WH: bit0 write fp32 C, bit1 write fp16 Ch.
// ---------------------------------------------------------------------------
#define HBK 32
#define ASTRIDE 80
#define SMH_A   0
#define SMH_W   10240
#define HSTG    20480
#define HSMEM   (2*HSTG)

template<int EPI, int WH>
__global__ __launch_bounds__(256, 1)
void hgemm_kernel(const __half* __restrict__ A, const __half* __restrict__ W,
                  const float* __restrict__ bias, const float* __restrict__ res,
                  float* __restrict__ C, __half* __restrict__ Ch,
                  int M, int N, int K)
{
    extern __shared__ __align__(16) char smem[];
    const uint32_t sb = s2u(smem);
    const int tid  = threadIdx.x;
    const int bm   = blockIdx.y * 128;
    const int bn   = blockIdx.x * 128;
    const int wid  = tid >> 5;
    const int lane = tid & 31;
    const int wm   = wid >> 2;
    const int wn   = wid & 3;

    float acc[4][4][4];
#pragma unroll
    for (int i = 0; i < 4; i++)
#pragma unroll
        for (int j = 0; j < 4; j++)
#pragma unroll
            for (int k = 0; k < 4; k++) acc[i][j][k] = 0.0f;

    uint4 ua[2], uh[2];

#define HLOAD(kc)                                                               \
    {                                                                           \
        const __half* Ab = A + (size_t)bm * K + (kc) * HBK;                     \
        const __half* Hb = W + (size_t)bn * K + (kc) * HBK;                     \
        _Pragma("unroll")                                                       \
        for (int i = 0; i < 2; i++) {                                           \
            int p = i * 256 + tid;                                              \
            int row = p >> 2, uc = p & 3;                                       \
            ua[i] = *(const uint4*)(Ab + (size_t)row * K + uc * 8);             \
            uh[i] = *(const uint4*)(Hb + (size_t)row * K + uc * 8);             \
        }                                                                       \
    }

#define HSTORE(s)                                                               \
    {                                                                           \
        char* sp = smem + (s) * HSTG;                                           \
        _Pragma("unroll")                                                       \
        for (int i = 0; i < 2; i++) {                                           \
            int p = i * 256 + tid;                                              \
            uint32_t off = (uint32_t)(p >> 2) * ASTRIDE + (uint32_t)(p & 3) * 16; \
            *(uint4*)(sp + SMH_A + off) = ua[i];                                \
            *(uint4*)(sp + SMH_W + off) = uh[i];                                \
        }                                                                       \
    }

    const int NC = K / HBK;
    HLOAD(0);
    HSTORE(0);
    __syncthreads();

    const uint32_t a_row = (uint32_t)(wm * 64) + (lane & 15);
    const uint32_t a_col = ((lane >> 4) & 1) * 16;
    const uint32_t b_row = (uint32_t)(wn * 32) + (lane & 7);
    const uint32_t b_col = ((lane >> 3) & 1) * 16;

    for (int kc = 0; kc < NC; kc++) {
        if (kc + 1 < NC) HLOAD(kc + 1);

        const uint32_t stg = sb + (uint32_t)(kc & 1) * HSTG;
#pragma unroll
        for (int s = 0; s < 2; s++) {
            uint32_t ah[4][4], wh[4][2];
            const uint32_t kb = s * 32;
#pragma unroll
            for (int mf = 0; mf < 4; mf++) {
                uint32_t ad = stg + SMH_A + (a_row + mf * 16) * ASTRIDE + kb + a_col;
                ldsm_x4(ah[mf], ad);
            }
#pragma unroll
            for (int nf = 0; nf < 4; nf++) {
                uint32_t bd = stg + SMH_W + (b_row + nf * 8) * ASTRIDE + kb + b_col;
                ldsm_x2(wh[nf], bd);
            }
#pragma unroll
            for (int mf = 0; mf < 4; mf++)
#pragma unroll
                for (int nf = 0; nf < 4; nf++)
                    mma_f16(acc[mf][nf], ah[mf], wh[nf]);
        }

        if (kc + 1 < NC) {
            HSTORE((kc + 1) & 1);
            __syncthreads();
        }
    }

    const int er = bm + wm * 64 + (lane >> 2);
    const int ec = bn + wn * 32 + (lane & 3) * 2;
#pragma unroll
    for (int mf = 0; mf < 4; mf++) {
#pragma unroll
        for (int nf = 0; nf < 4; nf++) {
            const int col = ec + nf * 8;
            const float b0 = bias[col], b1 = bias[col + 1];
#pragma unroll
            for (int h = 0; h < 2; h++) {
                const int row = er + mf * 16 + h * 8;
                float v0 = acc[mf][nf][2 * h + 0] * WUNSCALE + b0;
                float v1 = acc[mf][nf][2 * h + 1] * WUNSCALE + b1;
                const size_t go = (size_t)row * N + col;
                if (EPI == 1) {
                    float2 rv = *(const float2*)(res + go);
                    v0 += rv.x; v1 += rv.y;
                }
                if (EPI == 2) { v0 = gelu_f(v0); v1 = gelu_f(v1); }
                if (WH & 1) {
                    float2 o; o.x = v0; o.y = v1;
                    *(float2*)(C + go) = o;
                }
                if (WH & 2) {
                    __half2 hv = __floats2half2_rn(v0, v1);
                    *(__half2*)(Ch + go) = hv;
                }
            }
        }
    }
#undef HLOAD
#undef HSTORE
}

// ---------------------------------------------------------------------------
// LayerNorm (warp per row of 512); optional fp32 and fp16 outputs
// ---------------------------------------------------------------------------
__global__ void ln_kernel(const float* __restrict__ x, float* __restrict__ yf,
                          __half* __restrict__ yh,
                          const float* __restrict__ g, const float* __restrict__ b,
                          int rows)
{
    int warp = (blockIdx.x * blockDim.x + threadIdx.x) >> 5;
    int lane = threadIdx.x & 31;
    if (warp >= rows) return;
    const float* xr = x + (size_t)warp * HH;
    float v[16];
    float s = 0.0f;
#pragma unroll
    for (int i = 0; i < 16; i++) { v[i] = xr[i*32 + lane]; s += v[i]; }
#pragma unroll
    for (int o = 16; o > 0; o >>= 1) s += __shfl_xor_sync(0xffffffffu, s, o);
    float mean = s * (1.0f / HH);
    float sq = 0.0f;
#pragma unroll
    for (int i = 0; i < 16; i++) { float d = v[i] - mean; sq += d * d; }
#pragma unroll
    for (int o = 16; o > 0; o >>= 1) sq += __shfl_xor_sync(0xffffffffu, sq, o);
    float inv = rsqrtf(sq * (1.0f / HH) + 1e-5f);
#pragma unroll
    for (int i = 0; i < 16; i++) {
        int c = i*32 + lane;
        float val = (v[i] - mean) * inv * g[c] + b[c];
        if (yf) yf[(size_t)warp * HH + c] = val;
        if (yh) yh[(size_t)warp * HH + c] = __float2half_rn(val);
    }
}

// ---------------------------------------------------------------------------
// Attention: one block per (b, head). fp16 Q/KV in global, fp16 K/V in smem
// (32KB/block -> 7 blocks/SM), fp32 score/accumulate.
// ---------------------------------------------------------------------------
__global__ __launch_bounds__(64)
void attn_kernel(const __half* __restrict__ Q, const __half* __restrict__ KV,
                 __half* __restrict__ O, int Tq, int Tk, const int* __restrict__ lens)
{
    __shared__ __half Ks[64][64];
    __shared__ __half Vs[64][64];
    __shared__ float S[64][64];

    int b = blockIdx.x >> 3;
    int h = blockIdx.x & 7;
    int t = threadIdx.x;

    // KV row = 1024 halves = 512 uint32; K at +h*32 u32, V at +256 u32 further
    const uint32_t* kg = (const uint32_t*)(KV) + ((size_t)b * Tk) * 512 + h * 32;
    for (int i = t; i < Tk * 32; i += 64) {
        int r = i >> 5, c = i & 31;
        ((uint32_t*)Ks)[(r << 5) + c] = kg[(size_t)r * 512 + c];
        ((uint32_t*)Vs)[(r << 5) + c] = kg[(size_t)r * 512 + 256 + c];
    }
    __syncthreads();

    int limit = Tk;
    if (lens) { int l = lens[b]; limit = l < Tk ? l : Tk; }

    if (t < Tq) {
        const __half2* qrow = (const __half2*)(Q + ((size_t)b * Tq + t) * HH + h * DHH);
        float q[64];
#pragma unroll
        for (int kk = 0; kk < 32; kk++) {
            float2 f = __half22float2(qrow[kk]);
            q[2*kk] = f.x; q[2*kk+1] = f.y;
        }

        float mx = -1e30f;
        for (int j = 0; j < limit; j++) {
            const __half2* kr = (const __half2*)(&Ks[j][0]);
            float s = 0.0f;
#pragma unroll
            for (int kk = 0; kk < 32; kk++) {
                float2 f = __half22float2(kr[kk]);
                s += q[2*kk] * f.x + q[2*kk+1] * f.y;
            }
            s *= 0.125f;
            S[j][t] = s;
            mx = fmaxf(mx, s);
        }
        float den = 0.0f;
        for (int j = 0; j < limit; j++) {
            float e = expf(S[j][t] - mx);
            S[j][t] = e; den += e;
        }
        float inv = 1.0f / den;

        float acc[64];
#pragma unroll
        for (int kk = 0; kk < 64; kk++) acc[kk] = 0.0f;
        for (int j = 0; j < limit; j++) {
            float p = S[j][t];
            const __half2* vr = (const __half2*)(&Vs[j][0]);
#pragma unroll
            for (int kk = 0; kk < 32; kk++) {
                float2 f = __half22float2(vr[kk]);
                acc[2*kk]   += p * f.x;
                acc[2*kk+1] += p * f.y;
            }
        }
        __half2* orow = (__half2*)(O + ((size_t)b * Tq + t) * HH + h * DHH);
#pragma unroll
        for (int kk = 0; kk < 32; kk++)
            orow[kk] = __floats2half2_rn(acc[2*kk] * inv, acc[2*kk+1] * inv);
    }
}

// ---------------------------------------------------------------------------
// Small helpers
// ---------------------------------------------------------------------------
__global__ void small_linear(const float* __restrict__ X, const float* __restrict__ W,
                             const float* __restrict__ bias, float* __restrict__ Y,
                             int M, int N, int K)
{
    int idx = blockIdx.x * blockDim.x + threadIdx.x;
    if (idx >= M * N) return;
    int m = idx / N, n = idx % N;
    const float* xr = X + (size_t)m * K;
    const float* wr = W + (size_t)n * K;
    float acc = bias[n];
    for (int k = 0; k < K; k++) acc += xr[k] * wr[k];
    Y[idx] = acc;
}

__global__ void bcast_kernel(const float* __restrict__ src, float* __restrict__ dst,
                             int per, size_t total)
{
    for (size_t i = blockIdx.x * (size_t)blockDim.x + threadIdx.x; i < total;
         i += (size_t)gridDim.x * blockDim.x)
        dst[i] = src[i % per];
}

__global__ void build_c2_kernel(const float* __restrict__ c, const float* __restrict__ dbp,
                                float* __restrict__ out)
{
    size_t total = (size_t)BB * NI_ * HH;
    for (size_t idx = blockIdx.x * (size_t)blockDim.x + threadIdx.x; idx < total;
         idx += (size_t)gridDim.x * blockDim.x) {
        size_t col = idx % HH;
        size_t r   = (idx / HH) % NI_;
        size_t b   = idx / ((size_t)NI_ * HH);
        out[idx] = (r < CC) ? c[(b * CC + r) * HH + col] : dbp[(r - CC) * HH + col];
    }
}

__global__ void score_softmax_kernel(const float* __restrict__ qg, const float* __restrict__ P,
                                     int N, const int* __restrict__ lens,
                                     float* __restrict__ mu)
{
    __shared__ float sc[64];
    int b = blockIdx.x, t = threadIdx.x;
    float val = -1e30f;
    if (t < N) {
        bool valid = (lens == nullptr) || (t < lens[b]);
        if (valid) {
            const float* qr = qg + (size_t)b * HH;
            const float* pr = P + ((size_t)b * N + t) * HH;
            float acc = 0.0f;
            for (int k = 0; k < HH; k++) acc += qr[k] * pr[k];
            val = acc * 0.04419417382415922f;
        }
    }
    sc[t] = val;
    __syncthreads();
    float mx = -1e30f;
    for (int j = 0; j < N; j++) mx = fmaxf(mx, sc[j]);
    float sum = 0.0f;
    for (int j = 0; j < N; j++) sum += expf(sc[j] - mx);
    int stride = N + DD;
    if (t < N) mu[(size_t)b * stride + t] = expf(sc[t] - mx) / sum;
    if (t < DD) mu[(size_t)b * stride + N + t] = 1.0f / DD;
}

__global__ void build_norm_kernel(const float* __restrict__ nf, int Tn,
                                  const float* __restrict__ dbp,
                                  float* __restrict__ out, int Tall)
{
    int warp = (blockIdx.x * blockDim.x + threadIdx.x) >> 5;
    int lane = threadIdx.x & 31;
    int rows = BB * Tall;
    if (warp >= rows) return;
    int b = warp / Tall, r = warp % Tall;
    const float* src = (r < Tn) ? nf + ((size_t)b * Tn + r) * HH : dbp + (size_t)(r - Tn) * HH;
    float v[16];
    float sq = 0.0f;
#pragma unroll
    for (int i = 0; i < 16; i++) { v[i] = src[i*32 + lane]; sq += v[i]*v[i]; }
#pragma unroll
    for (int o = 16; o > 0; o >>= 1) sq += __shfl_xor_sync(0xffffffffu, sq, o);
    float inv = 1.0f / fmaxf(sqrtf(sq), 1e-12f);
    float* dst = out + (size_t)warp * HH;
#pragma unroll
    for (int i = 0; i < 16; i++) dst[i*32 + lane] = v[i] * inv;
}

__global__ void sim_kernel(const float* __restrict__ Ai, const float* __restrict__ At,
                           float* __restrict__ sim)
{
    int b = blockIdx.x;
    const float4* ab = (const float4*)(Ai + (size_t)b * 40 * HH);
    const float4* tb = (const float4*)(At + (size_t)b * 68 * HH);
    for (int p = threadIdx.x; p < 40 * 68; p += blockDim.x) {
        int i = p / 68, j = p % 68;
        const float4* ar = ab + i * (HH/4);
        const float4* tr = tb + j * (HH/4);
        float acc = 0.0f;
        for (int k = 0; k < HH/4; k++) {
            float4 a = ar[k], t = tr[k];
            acc += a.x*t.x + a.y*t.y + a.z*t.z + a.w*t.w;
        }
        sim[((size_t)b * 40 + i) * 68 + j] = acc;
    }
}

__global__ __launch_bounds__(128)
void sinkhorn_kernel(const float* __restrict__ sim, const float* __restrict__ mu,
                     const float* __restrict__ mv, float* __restrict__ out)
{
    __shared__ float Km[40*68];
    __shared__ float Sm[40*68];
    __shared__ float u[40], v[68], muS[40], mvS[68], red[128];
    int b = blockIdx.x, t = threadIdx.x;

    for (int p = t; p < 40*68; p += 128) {
        float s = sim[(size_t)b * 40*68 + p];
        Sm[p] = s;
        Km[p] = expf((s - 1.0f) * 10.0f);
    }
    if (t < 40) muS[t] = mu[(size_t)b*40 + t];
    if (t < 68) { mvS[t] = mv[(size_t)b*68 + t]; v[t] = 1.0f; }
    __syncthreads();

    for (int it = 0; it < 10; it++) {
        if (t < 40) {
            float s = 0.0f;
            for (int j = 0; j < 68; j++) s += Km[t*68 + j] * v[j];
            u[t] = muS[t] / s;
        }
        __syncthreads();
        if (t < 68) {
            float s = 0.0f;
            for (int i = 0; i < 40; i++) s += Km[i*68 + t] * u[i];
            v[t] = mvS[t] / s;
        }
        __syncthreads();
    }

    float acc = 0.0f;
    for (int p = t; p < NI_*NT_; p += 128) {
        int i = p / NT_, j = p % NT_;
        float k = Km[i*68 + j];
        acc += u[i] * k * v[j] * Sm[i*68 + j];
    }
    red[t] = acc;
    __syncthreads();
    for (int o = 64; o > 0; o >>= 1) {
        if (t < o) red[t] += red[t + o];
        __syncthreads();
    }
    if (t == 0) out[b] = red[0];
}

// ---------------------------------------------------------------------------
// Host-side helpers
// ---------------------------------------------------------------------------
static inline void gemm(cudaStream_t st, int epi, int wh, const __half* A,
                        const __half* W,
                        const float* bias, const float* res, float* C, __half* Ch,
                        int M, int N, int K)
{
    dim3 grid(N / 128, M / 128);
    if (epi == 0 && wh == 1)
        hgemm_kernel<0,1><<<grid, 256, HSMEM, st>>>(A, W, bias, res, C, Ch, M, N, K);
    else if (epi == 0 && wh == 2)
        hgemm_kernel<0,2><<<grid, 256, HSMEM, st>>>(A, W, bias, res, C, Ch, M, N, K);
    else if (epi == 0 && wh == 3)
        hgemm_kernel<0,3><<<grid, 256, HSMEM, st>>>(A, W, bias, res, C, Ch, M, N, K);
    else if (epi == 1)
        hgemm_kernel<1,1><<<grid, 256, HSMEM, st>>>(A, W, bias, res, C, Ch, M, N, K);
    else
        hgemm_kernel<2,2><<<grid, 256, HSMEM, st>>>(A, W, bias, res, C, Ch, M, N, K);
}

static inline void ln_run(cudaStream_t st, const float* x, float* yf, __half* yh,
                          const float* g, const float* b, int rows)
{
    int blocks = (rows + 7) / 8;
    ln_kernel<<<blocks, 256, 0, st>>>(x, yf, yh, g, b, rows);
}

struct Params {
    const float *attn_in_b, *attn_out_b, *ff1_b, *ff2_b, *lln_g, *lln_b;
    const int* lengths;
    float* base;
    __half* hb;
    __half* wb;
};

static void xlayer(const Params& P, cudaStream_t st, int lane,
                   const float* src, int Ts, float* tgt, int Tt,
                   int s, int l, bool masked)
{
    __half* hl = P.hb + HB_LANE + (size_t)lane * LANE_H;
    __half* wb = P.wb;
    __half* h_tgtln = hl + HL_TGT;
    __half* h_srcln = hl + HL_SRC;
    __half* h_ao    = hl + HL_AO;
    __half* h_hid   = hl + HL_HID;
    __half* h_q     = hl + HL_Q;
    __half* h_kv    = hl + HL_KV;

    const int Mt = BB * Tt, Ms = BB * Ts;
    const int sl = s * LL + l;
    const float* lg = P.lln_g + (size_t)sl * 3 * HH;
    const float* lb = P.lln_b + (size_t)sl * 3 * HH;
    const float* ib = P.attn_in_b  + (size_t)sl * 3 * HH;
    const float* ob = P.attn_out_b + (size_t)sl * HH;
    const float* f1b = P.ff1_b + (size_t)sl * 4 * HH;
    const float* f2b = P.ff2_b + (size_t)sl * HH;

    __half* ain  = wb + WO_AIN  + (size_t)sl * 3 * HH * HH;
    __half* aout = wb + WO_AOUT + (size_t)sl * HH * HH;
    __half* f1   = wb + WO_FF1  + (size_t)sl * 4 * HH * HH;
    __half* f2   = wb + WO_FF2  + (size_t)sl * 4 * HH * HH;

    ln_run(st, src, nullptr, h_srcln, lg + 0*HH, lb + 0*HH, Ms);
    ln_run(st, tgt, nullptr, h_tgtln, lg + 1*HH, lb + 1*HH, Mt);
    gemm(st, 0, 2, h_tgtln, ain, ib, nullptr, nullptr, h_q, Mt, HH, HH);
    gemm(st, 0, 2, h_srcln, ain + (size_t)HH*HH, ib + HH,
         nullptr, nullptr, h_kv, Ms, 2*HH, HH);
    attn_kernel<<<BB * NHH, 64, 0, st>>>(h_q, h_kv, h_ao, Tt, Ts,
                                         masked ? P.lengths : nullptr);
    gemm(st, 1, 1, h_ao, aout, ob, tgt, tgt, nullptr, Mt, HH, HH);
    ln_run(st, tgt, nullptr, h_tgtln, lg + 2*HH, lb + 2*HH, Mt);
    gemm(st, 2, 2, h_tgtln, f1, f1b, nullptr, nullptr, h_hid, Mt, 4*HH, HH);
    gemm(st, 1, 1, h_hid, f2, f2b, tgt, tgt, nullptr, Mt, HH, 4*HH);
}

// ---------------------------------------------------------------------------
// kernel_launch
// ---------------------------------------------------------------------------
extern "C" void kernel_launch(void* const* d_in, const int* in_sizes, int n_in,
                              void* d_out, int out_size)
{
    const float* img_global   = (const float*)d_in[0];
    const float* img_nodes    = (const float*)d_in[1];
    const float* txt_global   = (const float*)d_in[2];
    const float* txt_nodes    = (const float*)d_in[3];
    const int*   lengths      = (const int*)  d_in[4];
    const float* img_in_w     = (const float*)d_in[5];
    const float* img_in_b     = (const float*)d_in[6];
    const float* txt_in_w     = (const float*)d_in[7];
    const float* txt_in_b     = (const float*)d_in[8];
    const float* img_concepts = (const float*)d_in[9];
    const float* txt_concepts = (const float*)d_in[10];
    const float* img_dustbins = (const float*)d_in[11];
    const float* txt_dustbins = (const float*)d_in[12];
    const float* ln_g         = (const float*)d_in[13];
    const float* ln_b         = (const float*)d_in[14];
    const float* attn_in_w    = (const float*)d_in[15];
    const float* attn_in_b    = (const float*)d_in[16];
    const float* attn_out_w   = (const float*)d_in[17];
    const float* attn_out_b   = (const float*)d_in[18];
    const float* ff1_w        = (const float*)d_in[19];
    const float* ff1_b        = (const float*)d_in[20];
    const float* ff2_w        = (const float*)d_in[21];
    const float* ff2_b        = (const float*)d_in[22];
    const float* lln_g        = (const float*)d_in[23];
    const float* lln_b        = (const float*)d_in[24];
    const float* db_w         = (const float*)d_in[25];
    const float* db_b         = (const float*)d_in[26];
    const float* proj_w       = (const float*)d_in[27];
    const float* proj_b       = (const float*)d_in[28];
    const float* qg_w         = (const float*)d_in[29];
    const float* qg_b         = (const float*)d_in[30];
    float* out = (float*)d_out;

    cudaFuncSetAttribute(hgemm_kernel<0,1>, cudaFuncAttributeMaxDynamicSharedMemorySize, HSMEM);
    cudaFuncSetAttribute(hgemm_kernel<0,2>, cudaFuncAttributeMaxDynamicSharedMemorySize, HSMEM);
    cudaFuncSetAttribute(hgemm_kernel<0,3>, cudaFuncAttributeMaxDynamicSharedMemorySize, HSMEM);
    cudaFuncSetAttribute(hgemm_kernel<1,1>, cudaFuncAttributeMaxDynamicSharedMemorySize, HSMEM);
    cudaFuncSetAttribute(hgemm_kernel<2,2>, cudaFuncAttributeMaxDynamicSharedMemorySize, HSMEM);

    float* base = nullptr;
    cudaGetSymbolAddress((void**)&base, g_buf);
    __half* hb = nullptr;
    cudaGetSymbolAddress((void**)&hb, g_hbuf);
    __half* wb = nullptr;
    cudaGetSymbolAddress((void**)&wb, g_wbuf);

    // --- streams & events (created per call; host handles intentionally leaked:
    // kernel_launch runs only for correctness + capture, never per-replay) ---
    cudaStream_t sA = 0;            // legacy default stream (the captured one)
    cudaStream_t sB;
    cudaStreamCreateWithFlags(&sB, cudaStreamNonBlocking);
    cudaEvent_t evs[64];
    for (int i = 0; i < 64; i++) cudaEventCreateWithFlags(&evs[i], cudaEventDisableTiming);
    int evi = 0;
    auto forkto = [&](cudaStream_t to, cudaStream_t from) {
        cudaEventRecord(evs[evi], from);
        cudaStreamWaitEvent(to, evs[evi], 0);
        evi++;
    };
    auto joinAB = [&]() { forkto(sB, sA); forkto(sA, sB); };

    float* p_imgn  = base + O_IMGN;
    float* p_txtn  = base + O_TXTN;
    float* p_imgc  = base + O_IMGC;
    float* p_txtc  = base + O_TXTC;
    float* p_c2a   = base + O_C2A;
    float* p_c2b   = base + O_C2B;
    float* p_imgnf = base + O_IMGNF;
    float* p_txtnf = base + O_TXTNF;
    float* p_p2    = base + O_P2;
    float* p_p3    = base + O_P3;
    float* p_qi    = base + O_QI;
    float* p_qt    = base + O_QT;
    float* p_alli  = base + O_ALLI;
    float* p_allt  = base + O_ALLT;
    float* p_sim   = base + O_SIM;
    float* p_mu    = base + O_MU;
    float* p_mv    = base + O_MV;
    float* p_cn0   = base + O_CN0;
    float* p_cn1   = base + O_CN1;
    float* p_db0   = base + O_DB0;
    float* p_db1   = base + O_DB1;
    float* p_dbp   = base + O_DBP;
    float* p_dbp2  = base + O_DBP2;
    float* p_tmpA  = base + O_TMPA;
    float* p_tmpB  = base + O_TMPB;
    __half* hl0 = hb + HB_LANE;
    __half* hl1 = hb + HB_LANE + LANE_H;

    // fork B off the origin before any B work
    forkto(sB, sA);

    // --- weight/input conversion, split across streams ---
    wconv_kernel<<<1024, 256, 0, sA>>>(img_in_w,   wb + WO_IMGIN, SZ_IMGIN/4);
    wconv_kernel<<<2048, 256, 0, sA>>>(attn_in_w,  wb + WO_AIN,   SZ_AIN/4);
    wconv_kernel<<<2048, 256, 0, sA>>>(ff1_w,      wb + WO_FF1,   SZ_FF1/4);
    wconv_kernel<<<1024, 256, 0, sA>>>(proj_w,     wb + WO_PROJ,  SZ_PROJ/4);
    aconv_kernel<<<2048, 256, 0, sA>>>(img_nodes,  hb + HB_INI, (size_t)BB*NI_*DI_/4);
    aconv_kernel<<<512,  256, 0, sA>>>(img_global, hb + HB_GI,  (size_t)BB*GG/4);
    ln_run(sA, img_concepts, p_cn0, nullptr, ln_g + 4*HH, ln_b + 4*HH, CC);
    ln_run(sA, img_dustbins, p_db0, nullptr, ln_g + 6*HH, ln_b + 6*HH, DD);
    bcast_kernel<<<2048, 256, 0, sA>>>(p_cn0, p_imgc, CC*HH, (size_t)BB*CC*HH);

    wconv_kernel<<<1024, 256, 0, sB>>>(txt_in_w,   wb + WO_TXTIN, SZ_TXTIN/4);
    wconv_kernel<<<1024, 256, 0, sB>>>(attn_out_w, wb + WO_AOUT,  SZ_AOUT/4);
    wconv_kernel<<<2048, 256, 0, sB>>>(ff2_w,      wb + WO_FF2,   SZ_FF2/4);
    wconv_kernel<<<1024, 256, 0, sB>>>(qg_w,       wb + WO_QG,    SZ_QG/4);
    aconv_kernel<<<2048, 256, 0, sB>>>(txt_nodes,  hb + HB_INT, (size_t)BB*NT_*DT_/4);
    aconv_kernel<<<512,  256, 0, sB>>>(txt_global, hb + HB_GT,  (size_t)BB*GG/4);
    ln_run(sB, txt_concepts, p_cn1, nullptr, ln_g + 5*HH, ln_b + 5*HH, CC);
    ln_run(sB, txt_dustbins, p_db1, nullptr, ln_g + 7*HH, ln_b + 7*HH, DD);
    bcast_kernel<<<2048, 256, 0, sB>>>(p_cn1, p_txtc, CC*HH, (size_t)BB*CC*HH);

    // --- input projections + LN (A: img, B: txt) ---
    gemm(sA, 0, 1, hb + HB_INI, wb + WO_IMGIN, img_in_b,
         nullptr, p_tmpA, nullptr, BB*NI_, HH, DI_);
    ln_run(sA, p_tmpA, p_imgn, nullptr, ln_g + 0*HH, ln_b + 0*HH, BB*NI_);
    gemm(sB, 0, 1, hb + HB_INT, wb + WO_TXTIN, txt_in_b,
         nullptr, p_tmpB, nullptr, BB*NT_, HH, DT_);
    ln_run(sB, p_tmpB, p_txtn, nullptr, ln_g + 1*HH, ln_b + 1*HH, BB*NT_);

    Params P{attn_in_b, attn_out_b, ff1_b, ff2_b, lln_g, lln_b, lengths, base, hb, wb};

    // --- layers (A: img-side, B: txt-side; joins at true dependency points) ---
    for (int l = 0; l < LL; l++) {
        joinAB();
        xlayer(P, sA, 0, p_imgn, NI_, p_imgc, CC, 0, l, false);
        small_linear<<<(DD*HH + 255)/256, 256, 0, sA>>>(p_db0, db_w + (size_t)(0*LL + l)*HH*HH,
                                                        db_b + (size_t)(0*LL + l)*HH, p_dbp, DD, HH, HH);
        build_c2_kernel<<<4096, 256, 0, sA>>>(p_imgc, p_dbp, p_c2a);

        xlayer(P, sB, 1, p_txtn, NT_, p_txtc, CC, 1, l, true);
        small_linear<<<(DD*HH + 255)/256, 256, 0, sB>>>(p_db1, db_w + (size_t)(1*LL + l)*HH*HH,
                                                        db_b + (size_t)(1*LL + l)*HH, p_dbp2, DD, HH, HH);
        build_c2_kernel<<<4096, 256, 0, sB>>>(p_txtc, p_dbp2, p_c2b);

        joinAB();
        xlayer(P, sA, 0, p_c2a, NI_, p_txtn, NT_, 2, l, false);
        xlayer(P, sB, 1, p_c2b, NI_, p_imgn, NI_, 3, l, false);
    }
    joinAB();

    // --- tail (A: img-side, B: txt-side) ---
    __half* proj = wb + WO_PROJ;

    ln_run(sA, p_imgn, nullptr, hl0 + HL_SRC, ln_g + 2*HH, ln_b + 2*HH, BB*NI_);
    gemm(sA, 0, 3, hl0 + HL_SRC, proj, proj_b, nullptr,
         p_imgnf, hb + HB_IMGNF, BB*NI_, HH, HH);
    gemm(sA, 0, 1, hb + HB_IMGNF, proj + 2*(size_t)HH*HH,
         proj_b + 2*HH, nullptr, p_p2, nullptr, BB*NI_, HH, HH);
    gemm(sA, 0, 1, hb + HB_GI, wb + WO_QG, qg_b,
         nullptr, p_qi, nullptr, BB, HH, GG);
    score_softmax_kernel<<<BB, 64, 0, sA>>>(p_qi, p_p2, NI_, nullptr, p_mu);
    small_linear<<<(DD*HH + 255)/256, 256, 0, sA>>>(p_db0, proj_w + 4*(size_t)HH*HH,
                                                    proj_b + 4*HH, p_dbp, DD, HH, HH);
    build_norm_kernel<<<(BB*40*32 + 255)/256, 256, 0, sA>>>(p_imgnf, NI_, p_dbp, p_alli, 40);

    ln_run(sB, p_txtn, nullptr, hl1 + HL_SRC, ln_g + 3*HH, ln_b + 3*HH, BB*NT_);
    gemm(sB, 0, 3, hl1 + HL_SRC, proj + (size_t)HH*HH,
         proj_b + HH, nullptr, p_txtnf, hb + HB_TXTNF, BB*NT_, HH, HH);
    gemm(sB, 0, 1, hb + HB_TXTNF, proj + 3*(size_t)HH*HH,
         proj_b + 3*HH, nullptr, p_p3, nullptr, BB*NT_, HH, HH);
    gemm(sB, 0, 1, hb + HB_GT, wb + WO_QG + (size_t)HH*GG,
         qg_b + HH, nullptr, p_qt, nullptr, BB, HH, GG);
    score_softmax_kernel<<<BB, 64, 0, sB>>>(p_qt, p_p3, NT_, lengths, p_mv);
    small_linear<<<(DD*HH + 255)/256, 256, 0, sB>>>(p_db1, proj_w + 5*(size_t)HH*HH,
                                                    proj_b + 5*HH, p_dbp2, DD, HH, HH);
    build_norm_kernel<<<(BB*68*32 + 255)/256, 256, 0, sB>>>(p_txtnf, NT_, p_dbp2, p_allt, 68);

    // join B back into origin, finish on A
    forkto(sA, sB);
    sim_kernel<<<BB, 256, 0, sA>>>(p_alli, p_allt, p_sim);
    sinkhorn_kernel<<<BB, 128, 0, sA>>>(p_sim, p_mu, p_mv, out);
}

// round 11
// speedup vs baseline: 1.0036x; 1.0036x over previous
#include <cuda_runtime.h>
#include <cuda_fp16.h>
#include <math.h>
#include <stdint.h>

// ---------------------------------------------------------------------------
// Problem constants
// ---------------------------------------------------------------------------
#define BB   512
#define NI_  36
#define NT_  64
#define DI_  2048
#define DT_  768
#define GG   1024
#define HH   512
#define CC   32
#define DD   4
#define LL   2
#define NHH  8
#define DHH  64

constexpr size_t UU = (size_t)BB * NT_ * HH;   // 16.78M elements, the unit tile

// ---------------------------------------------------------------------------
// fp32 scratch
// ---------------------------------------------------------------------------
constexpr size_t O_IMGN  = 0;
constexpr size_t O_TXTN  = O_IMGN  + (size_t)BB*NI_*HH;
constexpr size_t O_IMGC  = O_TXTN  + UU;
constexpr size_t O_TXTC  = O_IMGC  + (size_t)BB*CC*HH;
constexpr size_t O_TMPA  = O_TXTC  + (size_t)BB*CC*HH;   // fp32 tmp lane A
constexpr size_t O_TMPB  = O_TMPA  + UU;                 // fp32 tmp lane B
constexpr size_t O_C2A   = O_TMPB  + UU;
constexpr size_t O_C2B   = O_C2A   + (size_t)BB*NI_*HH;
constexpr size_t O_IMGNF = O_C2B   + (size_t)BB*NI_*HH;
constexpr size_t O_TXTNF = O_IMGNF + (size_t)BB*NI_*HH;
constexpr size_t O_P2    = O_TXTNF + UU;
constexpr size_t O_P3    = O_P2    + (size_t)BB*NI_*HH;
constexpr size_t O_QI    = O_P3    + UU;
constexpr size_t O_QT    = O_QI    + (size_t)BB*HH;
constexpr size_t O_ALLI  = O_QT    + (size_t)BB*HH;
constexpr size_t O_ALLT  = O_ALLI  + (size_t)BB*40*HH;
constexpr size_t O_SIM   = O_ALLT  + (size_t)BB*68*HH;
constexpr size_t O_MU    = O_SIM   + (size_t)BB*40*68;
constexpr size_t O_MV    = O_MU    + (size_t)BB*40;
constexpr size_t O_CN0   = O_MV    + (size_t)BB*68;
constexpr size_t O_CN1   = O_CN0   + (size_t)CC*HH;
constexpr size_t O_DB0   = O_CN1   + (size_t)CC*HH;
constexpr size_t O_DB1   = O_DB0   + (size_t)DD*HH;
constexpr size_t O_DBP   = O_DB1   + (size_t)DD*HH;
constexpr size_t O_DBP2  = O_DBP   + (size_t)DD*HH;
constexpr size_t TOTAL_F = O_DBP2  + (size_t)DD*HH;
__device__ __align__(256) float g_buf[TOTAL_F];

// ---------------------------------------------------------------------------
// fp16 activation scratch (lane-private xlayer blocks + shared tail blocks)
// ---------------------------------------------------------------------------
constexpr size_t LANE_H   = 10 * UU;           // TGT+SRC+AO+HID(4U)+Q+KV(2U)
constexpr size_t HL_TGT   = 0;
constexpr size_t HL_SRC   = UU;
constexpr size_t HL_AO    = 2 * UU;
constexpr size_t HL_HID   = 3 * UU;
constexpr size_t HL_Q     = 7 * UU;
constexpr size_t HL_KV    = 8 * UU;            // 2U
constexpr size_t HB_LANE  = 0;
constexpr size_t HB_INI   = HB_LANE + 2 * LANE_H;
constexpr size_t HB_INT   = HB_INI  + (size_t)BB*NI_*DI_;
constexpr size_t HB_GI    = HB_INT  + (size_t)BB*NT_*DT_;
constexpr size_t HB_GT    = HB_GI   + (size_t)BB*GG;
constexpr size_t HB_IMGNF = HB_GT   + (size_t)BB*GG;
constexpr size_t HB_TXTNF = HB_IMGNF + (size_t)BB*NI_*HH;
constexpr size_t TOTAL_H  = HB_TXTNF + UU;
__device__ __align__(256) __half g_hbuf[TOTAL_H];

// ---------------------------------------------------------------------------
// fp16 weight scratch (single term, weights pre-scaled by 64)
// ---------------------------------------------------------------------------
constexpr size_t SZ_IMGIN = (size_t)HH*DI_;
constexpr size_t SZ_TXTIN = (size_t)HH*DT_;
constexpr size_t SZ_AIN   = (size_t)8*3*HH*HH;
constexpr size_t SZ_AOUT  = (size_t)8*HH*HH;
constexpr size_t SZ_FF1   = (size_t)8*4*HH*HH;
constexpr size_t SZ_FF2   = (size_t)8*4*HH*HH;
constexpr size_t SZ_PROJ  = (size_t)6*HH*HH;
constexpr size_t SZ_QG    = (size_t)2*HH*GG;
constexpr size_t WO_IMGIN = 0;
constexpr size_t WO_TXTIN = WO_IMGIN + SZ_IMGIN;
constexpr size_t WO_AIN   = WO_TXTIN + SZ_TXTIN;
constexpr size_t WO_AOUT  = WO_AIN   + SZ_AIN;
constexpr size_t WO_FF1   = WO_AOUT  + SZ_AOUT;
constexpr size_t WO_FF2   = WO_FF1   + SZ_FF1;
constexpr size_t WO_PROJ  = WO_FF2   + SZ_FF2;
constexpr size_t WO_QG    = WO_PROJ  + SZ_PROJ;
constexpr size_t TOTAL_W  = WO_QG    + SZ_QG;
__device__ __align__(256) __half g_wbuf[TOTAL_W];

#define WSCALE   64.0f
#define WUNSCALE 0.015625f

// ---------------------------------------------------------------------------
// PTX helpers (sm_80-era only)
// ---------------------------------------------------------------------------
__device__ __forceinline__ uint32_t s2u(const void* p) {
    uint32_t a;
    asm("{ .reg .u64 t; cvta.to.shared.u64 t, %1; cvt.u32.u64 %0, t; }"
        : "=r"(a) : "l"(p));
    return a;
}
__device__ __forceinline__ void ldsm_x4(uint32_t* r, uint32_t addr) {
    asm volatile("ldmatrix.sync.aligned.m8n8.x4.shared.b16 {%0,%1,%2,%3}, [%4];"
                 : "=r"(r[0]), "=r"(r[1]), "=r"(r[2]), "=r"(r[3]) : "r"(addr));
}
__device__ __forceinline__ void ldsm_x2(uint32_t* r, uint32_t addr) {
    asm volatile("ldmatrix.sync.aligned.m8n8.x2.shared.b16 {%0,%1}, [%2];"
                 : "=r"(r[0]), "=r"(r[1]) : "r"(addr));
}
__device__ __forceinline__ void mma_f16(float* c, const uint32_t* a, const uint32_t* b) {
    asm volatile(
        "mma.sync.aligned.m16n8k16.row.col.f32.f16.f16.f32 "
        "{%0,%1,%2,%3}, {%4,%5,%6,%7}, {%8,%9}, {%0,%1,%2,%3};"
        : "+f"(c[0]), "+f"(c[1]), "+f"(c[2]), "+f"(c[3])
        : "r"(a[0]), "r"(a[1]), "r"(a[2]), "r"(a[3]), "r"(b[0]), "r"(b[1]));
}
__device__ __forceinline__ float gelu_f(float x) {
    return 0.5f * x * (1.0f + erff(x * 0.7071067811865476f));
}

// ---------------------------------------------------------------------------
// Conversion kernels
// ---------------------------------------------------------------------------
__global__ void wconv_kernel(const float* __restrict__ w, __half* __restrict__ hi,
                             size_t n4)
{
    for (size_t i = blockIdx.x * (size_t)blockDim.x + threadIdx.x; i < n4;
         i += (size_t)gridDim.x * blockDim.x) {
        float4 f = reinterpret_cast<const float4*>(w)[i];
        __half2 H01 = __floats2half2_rn(f.x * WSCALE, f.y * WSCALE);
        __half2 H23 = __floats2half2_rn(f.z * WSCALE, f.w * WSCALE);
        uint2 Hv;
        Hv.x = *reinterpret_cast<uint32_t*>(&H01);
        Hv.y = *reinterpret_cast<uint32_t*>(&H23);
        reinterpret_cast<uint2*>(hi)[i] = Hv;
    }
}

__global__ void aconv_kernel(const float* __restrict__ x, __half* __restrict__ y, size_t n4)
{
    for (size_t i = blockIdx.x * (size_t)blockDim.x + threadIdx.x; i < n4;
         i += (size_t)gridDim.x * blockDim.x) {
        float4 f = reinterpret_cast<const float4*>(x)[i];
        __half2 a = __floats2half2_rn(f.x, f.y);
        __half2 b = __floats2half2_rn(f.z, f.w);
        uint2 o;
        o.x = *reinterpret_cast<uint32_t*>(&a);
        o.y = *reinterpret_cast<uint32_t*>(&b);
        reinterpret_cast<uint2*>(y)[i] = o;
    }
}

// ---------------------------------------------------------------------------
// fp16 tensor-core GEMM (single term): C = A @ W^T * 2^-6 + bias (+res/gelu)
// WH: bit0 write fp32 C, bit1 write fp16 Ch.
// ---------------------------------------------------------------------------
#define HBK 32
#define ASTRIDE 80
#define SMH_A   0
#define SMH_W   10240
#define HSTG    20480
#define HSMEM   (2*HSTG)

template<int EPI, int WH>
__global__ __launch_bounds__(256, 1)
void hgemm_kernel(const __half* __restrict__ A, const __half* __restrict__ W,
                  const float* __restrict__ bias, const float* __restrict__ res,
                  float* __restrict__ C, __half* __restrict__ Ch,
                  int M, int N, int K)
{
    extern __shared__ __align__(16) char smem[];
    const uint32_t sb = s2u(smem);
    const int tid  = threadIdx.x;
    const int bm   = blockIdx.y * 128;
    const int bn   = blockIdx.x * 128;
    const int wid  = tid >> 5;
    const int lane = tid & 31;
    const int wm   = wid >> 2;
    const int wn   = wid & 3;

    float acc[4][4][4];
#pragma unroll
    for (int i = 0; i < 4; i++)
#pragma unroll
        for (int j = 0; j < 4; j++)
#pragma unroll
            for (int k = 0; k < 4; k++) acc[i][j][k] = 0.0f;

    uint4 ua[2], uh[2];

#define HLOAD(kc)                                                               \
    {                                                                           \
        const __half* Ab = A + (size_t)bm * K + (kc) * HBK;                     \
        const __half* Hb = W + (size_t)bn * K + (kc) * HBK;                     \
        _Pragma("unroll")                                                       \
        for (int i = 0; i < 2; i++) {                                           \
            int p = i * 256 + tid;                                              \
            int row = p >> 2, uc = p & 3;                                       \
            ua[i] = *(const uint4*)(Ab + (size_t)row * K + uc * 8);             \
            uh[i] = *(const uint4*)(Hb + (size_t)row * K + uc * 8);             \
        }                                                                       \
    }

#define HSTORE(s)                                                               \
    {                                                                           \
        char* sp = smem + (s) * HSTG;                                           \
        _Pragma("unroll")                                                       \
        for (int i = 0; i < 2; i++) {                                           \
            int p = i * 256 + tid;                                              \
            uint32_t off = (uint32_t)(p >> 2) * ASTRIDE + (uint32_t)(p & 3) * 16; \
            *(uint4*)(sp + SMH_A + off) = ua[i];                                \
            *(uint4*)(sp + SMH_W + off) = uh[i];                                \
        }                                                                       \
    }

    const int NC = K / HBK;
    HLOAD(0);
    HSTORE(0);
    __syncthreads();

    const uint32_t a_row = (uint32_t)(wm * 64) + (lane & 15);
    const uint32_t a_col = ((lane >> 4) & 1) * 16;
    const uint32_t b_row = (uint32_t)(wn * 32) + (lane & 7);
    const uint32_t b_col = ((lane >> 3) & 1) * 16;

    for (int kc = 0; kc < NC; kc++) {
        if (kc + 1 < NC) HLOAD(kc + 1);

        const uint32_t stg = sb + (uint32_t)(kc & 1) * HSTG;
#pragma unroll
        for (int s = 0; s < 2; s++) {
            uint32_t ah[4][4], wh[4][2];
            const uint32_t kb = s * 32;
#pragma unroll
            for (int mf = 0; mf < 4; mf++) {
                uint32_t ad = stg + SMH_A + (a_row + mf * 16) * ASTRIDE + kb + a_col;
                ldsm_x4(ah[mf], ad);
            }
#pragma unroll
            for (int nf = 0; nf < 4; nf++) {
                uint32_t bd = stg + SMH_W + (b_row + nf * 8) * ASTRIDE + kb + b_col;
                ldsm_x2(wh[nf], bd);
            }
#pragma unroll
            for (int mf = 0; mf < 4; mf++)
#pragma unroll
                for (int nf = 0; nf < 4; nf++)
                    mma_f16(acc[mf][nf], ah[mf], wh[nf]);
        }

        if (kc + 1 < NC) {
            HSTORE((kc + 1) & 1);
            __syncthreads();
        }
    }

    const int er = bm + wm * 64 + (lane >> 2);
    const int ec = bn + wn * 32 + (lane & 3) * 2;
#pragma unroll
    for (int mf = 0; mf < 4; mf++) {
#pragma unroll
        for (int nf = 0; nf < 4; nf++) {
            const int col = ec + nf * 8;
            const float b0 = bias[col], b1 = bias[col + 1];
#pragma unroll
            for (int h = 0; h < 2; h++) {
                const int row = er + mf * 16 + h * 8;
                float v0 = acc[mf][nf][2 * h + 0] * WUNSCALE + b0;
                float v1 = acc[mf][nf][2 * h + 1] * WUNSCALE + b1;
                const size_t go = (size_t)row * N + col;
                if (EPI == 1) {
                    float2 rv = *(const float2*)(res + go);
                    v0 += rv.x; v1 += rv.y;
                }
                if (EPI == 2) { v0 = gelu_f(v0); v1 = gelu_f(v1); }
                if (WH & 1) {
                    float2 o; o.x = v0; o.y = v1;
                    *(float2*)(C + go) = o;
                }
                if (WH & 2) {
                    __half2 hv = __floats2half2_rn(v0, v1);
                    *(__half2*)(Ch + go) = hv;
                }
            }
        }
    }
#undef HLOAD
#undef HSTORE
}

// ---------------------------------------------------------------------------
// LayerNorm (warp per row of 512); optional fp32 and fp16 outputs
// ---------------------------------------------------------------------------
__global__ void ln_kernel(const float* __restrict__ x, float* __restrict__ yf,
                          __half* __restrict__ yh,
                          const float* __restrict__ g, const float* __restrict__ b,
                          int rows)
{
    int warp = (blockIdx.x * blockDim.x + threadIdx.x) >> 5;
    int lane = threadIdx.x & 31;
    if (warp >= rows) return;
    const float* xr = x + (size_t)warp * HH;
    float v[16];
    float s = 0.0f;
#pragma unroll
    for (int i = 0; i < 16; i++) { v[i] = xr[i*32 + lane]; s += v[i]; }
#pragma unroll
    for (int o = 16; o > 0; o >>= 1) s += __shfl_xor_sync(0xffffffffu, s, o);
    float mean = s * (1.0f / HH);
    float sq = 0.0f;
#pragma unroll
    for (int i = 0; i < 16; i++) { float d = v[i] - mean; sq += d * d; }
#pragma unroll
    for (int o = 16; o > 0; o >>= 1) sq += __shfl_xor_sync(0xffffffffu, sq, o);
    float inv = rsqrtf(sq * (1.0f / HH) + 1e-5f);
#pragma unroll
    for (int i = 0; i < 16; i++) {
        int c = i*32 + lane;
        float val = (v[i] - mean) * inv * g[c] + b[c];
        if (yf) yf[(size_t)warp * HH + c] = val;
        if (yh) yh[(size_t)warp * HH + c] = __float2half_rn(val);
    }
}

// ---------------------------------------------------------------------------
// Attention: one block per (b, head), 128 threads = (query q, half h2).
// fp16 Q/KV in global, converted ONCE to fp32 smem; fp32 float4 inner loops.
// Thread (q, h2): scores for j in its 32-j half, AV for its 32 output dims.
// ---------------------------------------------------------------------------
__global__ __launch_bounds__(128)
void attn_kernel(const __half* __restrict__ Q, const __half* __restrict__ KV,
                 __half* __restrict__ O, int Tq, int Tk, const int* __restrict__ lens)
{
    __shared__ float Ks[64][64];
    __shared__ float Vs[64][64];
    __shared__ float S[64][64];
    __shared__ float Mx[64][2];
    __shared__ float Den[64][2];

    const int b  = blockIdx.x >> 3;
    const int h  = blockIdx.x & 7;
    const int t  = threadIdx.x;
    const int q  = t & 63;
    const int h2 = t >> 6;

    // KV row = 1024 halves = 512 half2; K at half2 [h*32, +32), V at +256.
    const __half2* kg = (const __half2*)(KV) + ((size_t)b * Tk) * 512 + h * 32;
    for (int i = t; i < Tk * 32; i += 128) {
        int r = i >> 5, c = i & 31;
        float2 kf = __half22float2(kg[(size_t)r * 512 + c]);
        float2 vf = __half22float2(kg[(size_t)r * 512 + 256 + c]);
        Ks[r][2*c] = kf.x; Ks[r][2*c+1] = kf.y;
        Vs[r][2*c] = vf.x; Vs[r][2*c+1] = vf.y;
    }
    __syncthreads();

    int limit = Tk;
    if (lens) { int l = lens[b]; limit = l < Tk ? l : Tk; }

    const int j0 = h2 * 32;
    const int j1 = (j0 + 32 < limit) ? (j0 + 32) : limit;
    const bool active = (q < Tq);

    float qv[64];
    if (active) {
        const __half2* qrow = (const __half2*)(Q + ((size_t)b * Tq + q) * HH + h * DHH);
#pragma unroll
        for (int kk = 0; kk < 32; kk++) {
            float2 f = __half22float2(qrow[kk]);
            qv[2*kk] = f.x; qv[2*kk+1] = f.y;
        }
        float mx = -1e30f;
        for (int j = j0; j < j1; j++) {
            const float4* kr = (const float4*)(&Ks[j][0]);
            float s = 0.0f;
#pragma unroll
            for (int kk = 0; kk < 16; kk++) {
                float4 k4 = kr[kk];
                s += qv[4*kk]*k4.x + qv[4*kk+1]*k4.y + qv[4*kk+2]*k4.z + qv[4*kk+3]*k4.w;
            }
            s *= 0.125f;
            S[j][q] = s;
            mx = fmaxf(mx, s);
        }
        Mx[q][h2] = mx;
    }
    __syncthreads();

    if (active) {
        float mx = fmaxf(Mx[q][0], Mx[q][1]);
        float den = 0.0f;
        for (int j = j0; j < j1; j++) {
            float e = expf(S[j][q] - mx);
            S[j][q] = e;
            den += e;
        }
        Den[q][h2] = den;
    }
    __syncthreads();

    if (active) {
        const float inv = 1.0f / (Den[q][0] + Den[q][1]);
        const int dbase = h2 * 32;

        float acc[32];
#pragma unroll
        for (int kk = 0; kk < 32; kk++) acc[kk] = 0.0f;
        for (int j = 0; j < limit; j++) {
            float p = S[j][q];
            const float4* vr = (const float4*)(&Vs[j][dbase]);
#pragma unroll
            for (int kk = 0; kk < 8; kk++) {
                float4 v4 = vr[kk];
                acc[4*kk]   += p * v4.x; acc[4*kk+1] += p * v4.y;
                acc[4*kk+2] += p * v4.z; acc[4*kk+3] += p * v4.w;
            }
        }
        __half2* orow = (__half2*)(O + ((size_t)b * Tq + q) * HH + h * DHH + dbase);
#pragma unroll
        for (int kk = 0; kk < 16; kk++)
            orow[kk] = __floats2half2_rn(acc[2*kk] * inv, acc[2*kk+1] * inv);
    }
}

// ---------------------------------------------------------------------------
// Small helpers
// ---------------------------------------------------------------------------
__global__ void small_linear(const float* __restrict__ X, const float* __restrict__ W,
                             const float* __restrict__ bias, float* __restrict__ Y,
                             int M, int N, int K)
{
    int idx = blockIdx.x * blockDim.x + threadIdx.x;
    if (idx >= M * N) return;
    int m = idx / N, n = idx % N;
    const float* xr = X + (size_t)m * K;
    const float* wr = W + (size_t)n * K;
    float acc = bias[n];
    for (int k = 0; k < K; k++) acc += xr[k] * wr[k];
    Y[idx] = acc;
}

__global__ void bcast_kernel(const float* __restrict__ src, float* __restrict__ dst,
                             int per, size_t total)
{
    for (size_t i = blockIdx.x * (size_t)blockDim.x + threadIdx.x; i < total;
         i += (size_t)gridDim.x * blockDim.x)
        dst[i] = src[i % per];
}

__global__ void build_c2_kernel(const float* __restrict__ c, const float* __restrict__ dbp,
                                float* __restrict__ out)
{
    size_t total = (size_t)BB * NI_ * HH;
    for (size_t idx = blockIdx.x * (size_t)blockDim.x + threadIdx.x; idx < total;
         idx += (size_t)gridDim.x * blockDim.x) {
        size_t col = idx % HH;
        size_t r   = (idx / HH) % NI_;
        size_t b   = idx / ((size_t)NI_ * HH);
        out[idx] = (r < CC) ? c[(b * CC + r) * HH + col] : dbp[(r - CC) * HH + col];
    }
}

__global__ void score_softmax_kernel(const float* __restrict__ qg, const float* __restrict__ P,
                                     int N, const int* __restrict__ lens,
                                     float* __restrict__ mu)
{
    __shared__ float sc[64];
    int b = blockIdx.x, t = threadIdx.x;
    float val = -1e30f;
    if (t < N) {
        bool valid = (lens == nullptr) || (t < lens[b]);
        if (valid) {
            const float* qr = qg + (size_t)b * HH;
            const float* pr = P + ((size_t)b * N + t) * HH;
            float acc = 0.0f;
            for (int k = 0; k < HH; k++) acc += qr[k] * pr[k];
            val = acc * 0.04419417382415922f;
        }
    }
    sc[t] = val;
    __syncthreads();
    float mx = -1e30f;
    for (int j = 0; j < N; j++) mx = fmaxf(mx, sc[j]);
    float sum = 0.0f;
    for (int j = 0; j < N; j++) sum += expf(sc[j] - mx);
    int stride = N + DD;
    if (t < N) mu[(size_t)b * stride + t] = expf(sc[t] - mx) / sum;
    if (t < DD) mu[(size_t)b * stride + N + t] = 1.0f / DD;
}

__global__ void build_norm_kernel(const float* __restrict__ nf, int Tn,
                                  const float* __restrict__ dbp,
                                  float* __restrict__ out, int Tall)
{
    int warp = (blockIdx.x * blockDim.x + threadIdx.x) >> 5;
    int lane = threadIdx.x & 31;
    int rows = BB * Tall;
    if (warp >= rows) return;
    int b = warp / Tall, r = warp % Tall;
    const float* src = (r < Tn) ? nf + ((size_t)b * Tn + r) * HH : dbp + (size_t)(r - Tn) * HH;
    float v[16];
    float sq = 0.0f;
#pragma unroll
    for (int i = 0; i < 16; i++) { v[i] = src[i*32 + lane]; sq += v[i]*v[i]; }
#pragma unroll
    for (int o = 16; o > 0; o >>= 1) sq += __shfl_xor_sync(0xffffffffu, sq, o);
    float inv = 1.0f / fmaxf(sqrtf(sq), 1e-12f);
    float* dst = out + (size_t)warp * HH;
#pragma unroll
    for (int i = 0; i < 16; i++) dst[i*32 + lane] = v[i] * inv;
}

__global__ void sim_kernel(const float* __restrict__ Ai, const float* __restrict__ At,
                           float* __restrict__ sim)
{
    int b = blockIdx.x;
    const float4* ab = (const float4*)(Ai + (size_t)b * 40 * HH);
    const float4* tb = (const float4*)(At + (size_t)b * 68 * HH);
    for (int p = threadIdx.x; p < 40 * 68; p += blockDim.x) {
        int i = p / 68, j = p % 68;
        const float4* ar = ab + i * (HH/4);
        const float4* tr = tb + j * (HH/4);
        float acc = 0.0f;
        for (int k = 0; k < HH/4; k++) {
            float4 a = ar[k], t = tr[k];
            acc += a.x*t.x + a.y*t.y + a.z*t.z + a.w*t.w;
        }
        sim[((size_t)b * 40 + i) * 68 + j] = acc;
    }
}

__global__ __launch_bounds__(128)
void sinkhorn_kernel(const float* __restrict__ sim, const float* __restrict__ mu,
                     const float* __restrict__ mv, float* __restrict__ out)
{
    __shared__ float Km[40*68];
    __shared__ float Sm[40*68];
    __shared__ float u[40], v[68], muS[40], mvS[68], red[128];
    int b = blockIdx.x, t = threadIdx.x;

    for (int p = t; p < 40*68; p += 128) {
        float s = sim[(size_t)b * 40*68 + p];
        Sm[p] = s;
        Km[p] = expf((s - 1.0f) * 10.0f);
    }
    if (t < 40) muS[t] = mu[(size_t)b*40 + t];
    if (t < 68) { mvS[t] = mv[(size_t)b*68 + t]; v[t] = 1.0f; }
    __syncthreads();

    for (int it = 0; it < 10; it++) {
        if (t < 40) {
            float s = 0.0f;
            for (int j = 0; j < 68; j++) s += Km[t*68 + j] * v[j];
            u[t] = muS[t] / s;
        }
        __syncthreads();
        if (t < 68) {
            float s = 0.0f;
            for (int i = 0; i < 40; i++) s += Km[i*68 + t] * u[i];
            v[t] = mvS[t] / s;
        }
        __syncthreads();
    }

    float acc = 0.0f;
    for (int p = t; p < NI_*NT_; p += 128) {
        int i = p / NT_, j = p % NT_;
        float k = Km[i*68 + j];
        acc += u[i] * k * v[j] * Sm[i*68 + j];
    }
    red[t] = acc;
    __syncthreads();
    for (int o = 64; o > 0; o >>= 1) {
        if (t < o) red[t] += red[t + o];
        __syncthreads();
    }
    if (t == 0) out[b] = red[0];
}

// ---------------------------------------------------------------------------
// Host-side helpers
// ---------------------------------------------------------------------------
static inline void gemm(cudaStream_t st, int epi, int wh, const __half* A,
                        const __half* W,
                        const float* bias, const float* res, float* C, __half* Ch,
                        int M, int N, int K)
{
    dim3 grid(N / 128, M / 128);
    if (epi == 0 && wh == 1)
        hgemm_kernel<0,1><<<grid, 256, HSMEM, st>>>(A, W, bias, res, C, Ch, M, N, K);
    else if (epi == 0 && wh == 2)
        hgemm_kernel<0,2><<<grid, 256, HSMEM, st>>>(A, W, bias, res, C, Ch, M, N, K);
    else if (epi == 0 && wh == 3)
        hgemm_kernel<0,3><<<grid, 256, HSMEM, st>>>(A, W, bias, res, C, Ch, M, N, K);
    else if (epi == 1)
        hgemm_kernel<1,1><<<grid, 256, HSMEM, st>>>(A, W, bias, res, C, Ch, M, N, K);
    else
        hgemm_kernel<2,2><<<grid, 256, HSMEM, st>>>(A, W, bias, res, C, Ch, M, N, K);
}

static inline void ln_run(cudaStream_t st, const float* x, float* yf, __half* yh,
                          const float* g, const float* b, int rows)
{
    int blocks = (rows + 7) / 8;
    ln_kernel<<<blocks, 256, 0, st>>>(x, yf, yh, g, b, rows);
}

struct Params {
    const float *attn_in_b, *attn_out_b, *ff1_b, *ff2_b, *lln_g, *lln_b;
    const int* lengths;
    float* base;
    __half* hb;
    __half* wb;
};

static void xlayer(const Params& P, cudaStream_t st, int lane,
                   const float* src, int Ts, float* tgt, int Tt,
                   int s, int l, bool masked)
{
    __half* hl = P.hb + HB_LANE + (size_t)lane * LANE_H;
    __half* wb = P.wb;
    __half* h_tgtln = hl + HL_TGT;
    __half* h_srcln = hl + HL_SRC;
    __half* h_ao    = hl + HL_AO;
    __half* h_hid   = hl + HL_HID;
    __half* h_q     = hl + HL_Q;
    __half* h_kv    = hl + HL_KV;

    const int Mt = BB * Tt, Ms = BB * Ts;
    const int sl = s * LL + l;
    const float* lg = P.lln_g + (size_t)sl * 3 * HH;
    const float* lb = P.lln_b + (size_t)sl * 3 * HH;
    const float* ib = P.attn_in_b  + (size_t)sl * 3 * HH;
    const float* ob = P.attn_out_b + (size_t)sl * HH;
    const float* f1b = P.ff1_b + (size_t)sl * 4 * HH;
    const float* f2b = P.ff2_b + (size_t)sl * HH;

    __half* ain  = wb + WO_AIN  + (size_t)sl * 3 * HH * HH;
    __half* aout = wb + WO_AOUT + (size_t)sl * HH * HH;
    __half* f1   = wb + WO_FF1  + (size_t)sl * 4 * HH * HH;
    __half* f2   = wb + WO_FF2  + (size_t)sl * 4 * HH * HH;

    ln_run(st, src, nullptr, h_srcln, lg + 0*HH, lb + 0*HH, Ms);
    ln_run(st, tgt, nullptr, h_tgtln, lg + 1*HH, lb + 1*HH, Mt);
    gemm(st, 0, 2, h_tgtln, ain, ib, nullptr, nullptr, h_q, Mt, HH, HH);
    gemm(st, 0, 2, h_srcln, ain + (size_t)HH*HH, ib + HH,
         nullptr, nullptr, h_kv, Ms, 2*HH, HH);
    attn_kernel<<<BB * NHH, 128, 0, st>>>(h_q, h_kv, h_ao, Tt, Ts,
                                          masked ? P.lengths : nullptr);
    gemm(st, 1, 1, h_ao, aout, ob, tgt, tgt, nullptr, Mt, HH, HH);
    ln_run(st, tgt, nullptr, h_tgtln, lg + 2*HH, lb + 2*HH, Mt);
    gemm(st, 2, 2, h_tgtln, f1, f1b, nullptr, nullptr, h_hid, Mt, 4*HH, HH);
    gemm(st, 1, 1, h_hid, f2, f2b, tgt, tgt, nullptr, Mt, HH, 4*HH);
}

// ---------------------------------------------------------------------------
// kernel_launch
// ---------------------------------------------------------------------------
extern "C" void kernel_launch(void* const* d_in, const int* in_sizes, int n_in,
                              void* d_out, int out_size)
{
    const float* img_global   = (const float*)d_in[0];
    const float* img_nodes    = (const float*)d_in[1];
    const float* txt_global   = (const float*)d_in[2];
    const float* txt_nodes    = (const float*)d_in[3];
    const int*   lengths      = (const int*)  d_in[4];
    const float* img_in_w     = (const float*)d_in[5];
    const float* img_in_b     = (const float*)d_in[6];
    const float* txt_in_w     = (const float*)d_in[7];
    const float* txt_in_b     = (const float*)d_in[8];
    const float* img_concepts = (const float*)d_in[9];
    const float* txt_concepts = (const float*)d_in[10];
    const float* img_dustbins = (const float*)d_in[11];
    const float* txt_dustbins = (const float*)d_in[12];
    const float* ln_g         = (const float*)d_in[13];
    const float* ln_b         = (const float*)d_in[14];
    const float* attn_in_w    = (const float*)d_in[15];
    const float* attn_in_b    = (const float*)d_in[16];
    const float* attn_out_w   = (const float*)d_in[17];
    const float* attn_out_b   = (const float*)d_in[18];
    const float* ff1_w        = (const float*)d_in[19];
    const float* ff1_b        = (const float*)d_in[20];
    const float* ff2_w        = (const float*)d_in[21];
    const float* ff2_b        = (const float*)d_in[22];
    const float* lln_g        = (const float*)d_in[23];
    const float* lln_b        = (const float*)d_in[24];
    const float* db_w         = (const float*)d_in[25];
    const float* db_b         = (const float*)d_in[26];
    const float* proj_w       = (const float*)d_in[27];
    const float* proj_b       = (const float*)d_in[28];
    const float* qg_w         = (const float*)d_in[29];
    const float* qg_b         = (const float*)d_in[30];
    float* out = (float*)d_out;

    cudaFuncSetAttribute(hgemm_kernel<0,1>, cudaFuncAttributeMaxDynamicSharedMemorySize, HSMEM);
    cudaFuncSetAttribute(hgemm_kernel<0,2>, cudaFuncAttributeMaxDynamicSharedMemorySize, HSMEM);
    cudaFuncSetAttribute(hgemm_kernel<0,3>, cudaFuncAttributeMaxDynamicSharedMemorySize, HSMEM);
    cudaFuncSetAttribute(hgemm_kernel<1,1>, cudaFuncAttributeMaxDynamicSharedMemorySize, HSMEM);
    cudaFuncSetAttribute(hgemm_kernel<2,2>, cudaFuncAttributeMaxDynamicSharedMemorySize, HSMEM);

    float* base = nullptr;
    cudaGetSymbolAddress((void**)&base, g_buf);
    __half* hb = nullptr;
    cudaGetSymbolAddress((void**)&hb, g_hbuf);
    __half* wb = nullptr;
    cudaGetSymbolAddress((void**)&wb, g_wbuf);

    // --- streams & events (created per call; host handles intentionally leaked:
    // kernel_launch runs only for correctness + capture, never per-replay) ---
    cudaStream_t sA = 0;            // legacy default stream (the captured one)
    cudaStream_t sB;
    cudaStreamCreateWithFlags(&sB, cudaStreamNonBlocking);
    cudaEvent_t evs[64];
    for (int i = 0; i < 64; i++) cudaEventCreateWithFlags(&evs[i], cudaEventDisableTiming);
    int evi = 0;
    auto forkto = [&](cudaStream_t to, cudaStream_t from) {
        cudaEventRecord(evs[evi], from);
        cudaStreamWaitEvent(to, evs[evi], 0);
        evi++;
    };
    auto joinAB = [&]() { forkto(sB, sA); forkto(sA, sB); };

    float* p_imgn  = base + O_IMGN;
    float* p_txtn  = base + O_TXTN;
    float* p_imgc  = base + O_IMGC;
    float* p_txtc  = base + O_TXTC;
    float* p_c2a   = base + O_C2A;
    float* p_c2b   = base + O_C2B;
    float* p_imgnf = base + O_IMGNF;
    float* p_txtnf = base + O_TXTNF;
    float* p_p2    = base + O_P2;
    float* p_p3    = base + O_P3;
    float* p_qi    = base + O_QI;
    float* p_qt    = base + O_QT;
    float* p_alli  = base + O_ALLI;
    float* p_allt  = base + O_ALLT;
    float* p_sim   = base + O_SIM;
    float* p_mu    = base + O_MU;
    float* p_mv    = base + O_MV;
    float* p_cn0   = base + O_CN0;
    float* p_cn1   = base + O_CN1;
    float* p_db0   = base + O_DB0;
    float* p_db1   = base + O_DB1;
    float* p_dbp   = base + O_DBP;
    float* p_dbp2  = base + O_DBP2;
    float* p_tmpA  = base + O_TMPA;
    float* p_tmpB  = base + O_TMPB;
    __half* hl0 = hb + HB_LANE;
    __half* hl1 = hb + HB_LANE + LANE_H;

    // fork B off the origin before any B work
    forkto(sB, sA);

    // --- weight/input conversion, split across streams ---
    wconv_kernel<<<1024, 256, 0, sA>>>(img_in_w,   wb + WO_IMGIN, SZ_IMGIN/4);
    wconv_kernel<<<2048, 256, 0, sA>>>(attn_in_w,  wb + WO_AIN,   SZ_AIN/4);
    wconv_kernel<<<2048, 256, 0, sA>>>(ff1_w,      wb + WO_FF1,   SZ_FF1/4);
    wconv_kernel<<<1024, 256, 0, sA>>>(proj_w,     wb + WO_PROJ,  SZ_PROJ/4);
    aconv_kernel<<<2048, 256, 0, sA>>>(img_nodes,  hb + HB_INI, (size_t)BB*NI_*DI_/4);
    aconv_kernel<<<512,  256, 0, sA>>>(img_global, hb + HB_GI,  (size_t)BB*GG/4);
    ln_run(sA, img_concepts, p_cn0, nullptr, ln_g + 4*HH, ln_b + 4*HH, CC);
    ln_run(sA, img_dustbins, p_db0, nullptr, ln_g + 6*HH, ln_b + 6*HH, DD);
    bcast_kernel<<<2048, 256, 0, sA>>>(p_cn0, p_imgc, CC*HH, (size_t)BB*CC*HH);

    wconv_kernel<<<1024, 256, 0, sB>>>(txt_in_w,   wb + WO_TXTIN, SZ_TXTIN/4);
    wconv_kernel<<<1024, 256, 0, sB>>>(attn_out_w, wb + WO_AOUT,  SZ_AOUT/4);
    wconv_kernel<<<2048, 256, 0, sB>>>(ff2_w,      wb + WO_FF2,   SZ_FF2/4);
    wconv_kernel<<<1024, 256, 0, sB>>>(qg_w,       wb + WO_QG,    SZ_QG/4);
    aconv_kernel<<<2048, 256, 0, sB>>>(txt_nodes,  hb + HB_INT, (size_t)BB*NT_*DT_/4);
    aconv_kernel<<<512,  256, 0, sB>>>(txt_global, hb + HB_GT,  (size_t)BB*GG/4);
    ln_run(sB, txt_concepts, p_cn1, nullptr, ln_g + 5*HH, ln_b + 5*HH, CC);
    ln_run(sB, txt_dustbins, p_db1, nullptr, ln_g + 7*HH, ln_b + 7*HH, DD);
    bcast_kernel<<<2048, 256, 0, sB>>>(p_cn1, p_txtc, CC*HH, (size_t)BB*CC*HH);

    // --- input projections + LN (A: img, B: txt) ---
    gemm(sA, 0, 1, hb + HB_INI, wb + WO_IMGIN, img_in_b,
         nullptr, p_tmpA, nullptr, BB*NI_, HH, DI_);
    ln_run(sA, p_tmpA, p_imgn, nullptr, ln_g + 0*HH, ln_b + 0*HH, BB*NI_);
    gemm(sB, 0, 1, hb + HB_INT, wb + WO_TXTIN, txt_in_b,
         nullptr, p_tmpB, nullptr, BB*NT_, HH, DT_);
    ln_run(sB, p_tmpB, p_txtn, nullptr, ln_g + 1*HH, ln_b + 1*HH, BB*NT_);

    Params P{attn_in_b, attn_out_b, ff1_b, ff2_b, lln_g, lln_b, lengths, base, hb, wb};

    // --- layers (A: img-side, B: txt-side; joins at true dependency points) ---
    for (int l = 0; l < LL; l++) {
        joinAB();
        xlayer(P, sA, 0, p_imgn, NI_, p_imgc, CC, 0, l, false);
        small_linear<<<(DD*HH + 255)/256, 256, 0, sA>>>(p_db0, db_w + (size_t)(0*LL + l)*HH*HH,
                                                        db_b + (size_t)(0*LL + l)*HH, p_dbp, DD, HH, HH);
        build_c2_kernel<<<4096, 256, 0, sA>>>(p_imgc, p_dbp, p_c2a);

        xlayer(P, sB, 1, p_txtn, NT_, p_txtc, CC, 1, l, true);
        small_linear<<<(DD*HH + 255)/256, 256, 0, sB>>>(p_db1, db_w + (size_t)(1*LL + l)*HH*HH,
                                                        db_b + (size_t)(1*LL + l)*HH, p_dbp2, DD, HH, HH);
        build_c2_kernel<<<4096, 256, 0, sB>>>(p_txtc, p_dbp2, p_c2b);

        joinAB();
        xlayer(P, sA, 0, p_c2a, NI_, p_txtn, NT_, 2, l, false);
        xlayer(P, sB, 1, p_c2b, NI_, p_imgn, NI_, 3, l, false);
    }
    joinAB();

    // --- tail (A: img-side, B: txt-side) ---
    __half* proj = wb + WO_PROJ;

    ln_run(sA, p_imgn, nullptr, hl0 + HL_SRC, ln_g + 2*HH, ln_b + 2*HH, BB*NI_);
    gemm(sA, 0, 3, hl0 + HL_SRC, proj, proj_b, nullptr,
         p_imgnf, hb + HB_IMGNF, BB*NI_, HH, HH);
    gemm(sA, 0, 1, hb + HB_IMGNF, proj + 2*(size_t)HH*HH,
         proj_b + 2*HH, nullptr, p_p2, nullptr, BB*NI_, HH, HH);
    gemm(sA, 0, 1, hb + HB_GI, wb + WO_QG, qg_b,
         nullptr, p_qi, nullptr, BB, HH, GG);
    score_softmax_kernel<<<BB, 64, 0, sA>>>(p_qi, p_p2, NI_, nullptr, p_mu);
    small_linear<<<(DD*HH + 255)/256, 256, 0, sA>>>(p_db0, proj_w + 4*(size_t)HH*HH,
                                                    proj_b + 4*HH, p_dbp, DD, HH, HH);
    build_norm_kernel<<<(BB*40*32 + 255)/256, 256, 0, sA>>>(p_imgnf, NI_, p_dbp, p_alli, 40);

    ln_run(sB, p_txtn, nullptr, hl1 + HL_SRC, ln_g + 3*HH, ln_b + 3*HH, BB*NT_);
    gemm(sB, 0, 3, hl1 + HL_SRC, proj + (size_t)HH*HH,
         proj_b + HH, nullptr, p_txtnf, hb + HB_TXTNF, BB*NT_, HH, HH);
    gemm(sB, 0, 1, hb + HB_TXTNF, proj + 3*(size_t)HH*HH,
         proj_b + 3*HH, nullptr, p_p3, nullptr, BB*NT_, HH, HH);
    gemm(sB, 0, 1, hb + HB_GT, wb + WO_QG + (size_t)HH*GG,
         qg_b + HH, nullptr, p_qt, nullptr, BB, HH, GG);
    score_softmax_kernel<<<BB, 64, 0, sB>>>(p_qt, p_p3, NT_, lengths, p_mv);
    small_linear<<<(DD*HH + 255)/256, 256, 0, sB>>>(p_db1, proj_w + 5*(size_t)HH*HH,
                                                    proj_b + 5*HH, p_dbp2, DD, HH, HH);
    build_norm_kernel<<<(BB*68*32 + 255)/256, 256, 0, sB>>>(p_txtnf, NT_, p_dbp2, p_allt, 68);

    // join B back into origin, finish on A
    forkto(sA, sB);
    sim_kernel<<<BB, 256, 0, sA>>>(p_alli, p_allt, p_sim);
    sinkhorn_kernel<<<BB, 128, 0, sA>>>(p_sim, p_mu, p_mv, out);
}

// round 12
// speedup vs baseline: 1.2090x; 1.2047x over previous
#include <cuda_runtime.h>
#include <cuda_fp16.h>
#include <math.h>
#include <stdint.h>

// ---------------------------------------------------------------------------
// Problem constants
// ---------------------------------------------------------------------------
#define BB   512
#define NI_  36
#define NT_  64
#define DI_  2048
#define DT_  768
#define GG   1024
#define HH   512
#define CC   32
#define DD   4
#define LL   2
#define NHH  8
#define DHH  64

constexpr size_t UU = (size_t)BB * NT_ * HH;   // 16.78M elements, the unit tile

// ---------------------------------------------------------------------------
// fp32 scratch (lane0/lane1 get private Q/KV blocks)
// ---------------------------------------------------------------------------
constexpr size_t O_IMGN  = 0;
constexpr size_t O_TXTN  = O_IMGN  + (size_t)BB*NI_*HH;
constexpr size_t O_IMGC  = O_TXTN  + UU;
constexpr size_t O_TXTC  = O_IMGC  + (size_t)BB*CC*HH;
constexpr size_t O_LANEF = O_TXTC  + (size_t)BB*CC*HH;   // 2 lanes x (Q + KV)
constexpr size_t LANE_F  = 3 * UU;                        // Q (1U) + KV (2U)
constexpr size_t OL_Q    = 0;
constexpr size_t OL_KV   = UU;
constexpr size_t O_C2A   = O_LANEF + 2 * LANE_F;
constexpr size_t O_C2B   = O_C2A   + (size_t)BB*NI_*HH;
constexpr size_t O_IMGNF = O_C2B   + (size_t)BB*NI_*HH;
constexpr size_t O_TXTNF = O_IMGNF + (size_t)BB*NI_*HH;
constexpr size_t O_P2    = O_TXTNF + UU;
constexpr size_t O_P3    = O_P2    + (size_t)BB*NI_*HH;
constexpr size_t O_QI    = O_P3    + UU;
constexpr size_t O_QT    = O_QI    + (size_t)BB*HH;
constexpr size_t O_ALLI  = O_QT    + (size_t)BB*HH;
constexpr size_t O_ALLT  = O_ALLI  + (size_t)BB*40*HH;
constexpr size_t O_SIM   = O_ALLT  + (size_t)BB*68*HH;
constexpr size_t O_MU    = O_SIM   + (size_t)BB*40*68;
constexpr size_t O_MV    = O_MU    + (size_t)BB*40;
constexpr size_t O_CN0   = O_MV    + (size_t)BB*68;
constexpr size_t O_CN1   = O_CN0   + (size_t)CC*HH;
constexpr size_t O_DB0   = O_CN1   + (size_t)CC*HH;
constexpr size_t O_DB1   = O_DB0   + (size_t)DD*HH;
constexpr size_t O_DBP   = O_DB1   + (size_t)DD*HH;
constexpr size_t O_DBP2  = O_DBP   + (size_t)DD*HH;
constexpr size_t TOTAL_F = O_DBP2  + (size_t)DD*HH;
__device__ __align__(256) float g_buf[TOTAL_F];

// ---------------------------------------------------------------------------
// fp16 activation scratch (lane-private xlayer blocks + shared tail blocks)
// ---------------------------------------------------------------------------
constexpr size_t LANE_H   = 7 * UU;            // TGT + SRC + AO + HID(4U)
constexpr size_t HL_TGT   = 0;
constexpr size_t HL_SRC   = UU;
constexpr size_t HL_AO    = 2 * UU;
constexpr size_t HL_HID   = 3 * UU;
constexpr size_t HB_LANE  = 0;
constexpr size_t HB_INI   = HB_LANE + 2 * LANE_H;
constexpr size_t HB_INT   = HB_INI  + (size_t)BB*NI_*DI_;
constexpr size_t HB_GI    = HB_INT  + (size_t)BB*NT_*DT_;
constexpr size_t HB_GT    = HB_GI   + (size_t)BB*GG;
constexpr size_t HB_IMGNF = HB_GT   + (size_t)BB*GG;
constexpr size_t HB_TXTNF = HB_IMGNF + (size_t)BB*NI_*HH;
constexpr size_t TOTAL_H  = HB_TXTNF + UU;
__device__ __align__(256) __half g_hbuf[TOTAL_H];

// ---------------------------------------------------------------------------
// fp16 weight scratch (single term, weights pre-scaled by 64)
// ---------------------------------------------------------------------------
constexpr size_t SZ_IMGIN = (size_t)HH*DI_;
constexpr size_t SZ_TXTIN = (size_t)HH*DT_;
constexpr size_t SZ_AIN   = (size_t)8*3*HH*HH;
constexpr size_t SZ_AOUT  = (size_t)8*HH*HH;
constexpr size_t SZ_FF1   = (size_t)8*4*HH*HH;
constexpr size_t SZ_FF2   = (size_t)8*4*HH*HH;
constexpr size_t SZ_PROJ  = (size_t)6*HH*HH;
constexpr size_t SZ_QG    = (size_t)2*HH*GG;
constexpr size_t WO_IMGIN = 0;
constexpr size_t WO_TXTIN = WO_IMGIN + SZ_IMGIN;
constexpr size_t WO_AIN   = WO_TXTIN + SZ_TXTIN;
constexpr size_t WO_AOUT  = WO_AIN   + SZ_AIN;
constexpr size_t WO_FF1   = WO_AOUT  + SZ_AOUT;
constexpr size_t WO_FF2   = WO_FF1   + SZ_FF1;
constexpr size_t WO_PROJ  = WO_FF2   + SZ_FF2;
constexpr size_t WO_QG    = WO_PROJ  + SZ_PROJ;
constexpr size_t TOTAL_W  = WO_QG    + SZ_QG;
__device__ __align__(256) __half g_wbuf[TOTAL_W];

#define WSCALE   64.0f
#define WUNSCALE 0.015625f

// ---------------------------------------------------------------------------
// PTX helpers (sm_80-era only)
// ---------------------------------------------------------------------------
__device__ __forceinline__ uint32_t s2u(const void* p) {
    uint32_t a;
    asm("{ .reg .u64 t; cvta.to.shared.u64 t, %1; cvt.u32.u64 %0, t; }"
        : "=r"(a) : "l"(p));
    return a;
}
__device__ __forceinline__ void ldsm_x4(uint32_t* r, uint32_t addr) {
    asm volatile("ldmatrix.sync.aligned.m8n8.x4.shared.b16 {%0,%1,%2,%3}, [%4];"
                 : "=r"(r[0]), "=r"(r[1]), "=r"(r[2]), "=r"(r[3]) : "r"(addr));
}
__device__ __forceinline__ void ldsm_x2(uint32_t* r, uint32_t addr) {
    asm volatile("ldmatrix.sync.aligned.m8n8.x2.shared.b16 {%0,%1}, [%2];"
                 : "=r"(r[0]), "=r"(r[1]) : "r"(addr));
}
__device__ __forceinline__ void mma_f16(float* c, const uint32_t* a, const uint32_t* b) {
    asm volatile(
        "mma.sync.aligned.m16n8k16.row.col.f32.f16.f16.f32 "
        "{%0,%1,%2,%3}, {%4,%5,%6,%7}, {%8,%9}, {%0,%1,%2,%3};"
        : "+f"(c[0]), "+f"(c[1]), "+f"(c[2]), "+f"(c[3])
        : "r"(a[0]), "r"(a[1]), "r"(a[2]), "r"(a[3]), "r"(b[0]), "r"(b[1]));
}
__device__ __forceinline__ float gelu_f(float x) {
    return 0.5f * x * (1.0f + erff(x * 0.7071067811865476f));
}

// ---------------------------------------------------------------------------
// Conversion kernels
// ---------------------------------------------------------------------------
__global__ void wconv_kernel(const float* __restrict__ w, __half* __restrict__ hi,
                             size_t n4)
{
    for (size_t i = blockIdx.x * (size_t)blockDim.x + threadIdx.x; i < n4;
         i += (size_t)gridDim.x * blockDim.x) {
        float4 f = reinterpret_cast<const float4*>(w)[i];
        __half2 H01 = __floats2half2_rn(f.x * WSCALE, f.y * WSCALE);
        __half2 H23 = __floats2half2_rn(f.z * WSCALE, f.w * WSCALE);
        uint2 Hv;
        Hv.x = *reinterpret_cast<uint32_t*>(&H01);
        Hv.y = *reinterpret_cast<uint32_t*>(&H23);
        reinterpret_cast<uint2*>(hi)[i] = Hv;
    }
}

__global__ void aconv_kernel(const float* __restrict__ x, __half* __restrict__ y, size_t n4)
{
    for (size_t i = blockIdx.x * (size_t)blockDim.x + threadIdx.x; i < n4;
         i += (size_t)gridDim.x * blockDim.x) {
        float4 f = reinterpret_cast<const float4*>(x)[i];
        __half2 a = __floats2half2_rn(f.x, f.y);
        __half2 b = __floats2half2_rn(f.z, f.w);
        uint2 o;
        o.x = *reinterpret_cast<uint32_t*>(&a);
        o.y = *reinterpret_cast<uint32_t*>(&b);
        reinterpret_cast<uint2*>(y)[i] = o;
    }
}

// ---------------------------------------------------------------------------
// fp16 tensor-core GEMM (single term): C = A @ W^T * 2^-6 + bias (+res/gelu)
// WH: bit0 write fp32 C, bit1 write fp16 Ch.  2 CTAs/SM for latency hiding.
// ---------------------------------------------------------------------------
#define HBK 32
#define ASTRIDE 80
#define SMH_A   0
#define SMH_W   10240
#define HSTG    20480
#define HSMEM   (2*HSTG)

template<int EPI, int WH>
__global__ __launch_bounds__(256, 2)
void hgemm_kernel(const __half* __restrict__ A, const __half* __restrict__ W,
                  const float* __restrict__ bias, const float* __restrict__ res,
                  float* __restrict__ C, __half* __restrict__ Ch,
                  int M, int N, int K)
{
    extern __shared__ __align__(16) char smem[];
    const uint32_t sb = s2u(smem);
    const int tid  = threadIdx.x;
    const int bm   = blockIdx.y * 128;
    const int bn   = blockIdx.x * 128;
    const int wid  = tid >> 5;
    const int lane = tid & 31;
    const int wm   = wid >> 2;
    const int wn   = wid & 3;

    float acc[4][4][4];
#pragma unroll
    for (int i = 0; i < 4; i++)
#pragma unroll
        for (int j = 0; j < 4; j++)
#pragma unroll
            for (int k = 0; k < 4; k++) acc[i][j][k] = 0.0f;

    uint4 ua[2], uh[2];

#define HLOAD(kc)                                                               \
    {                                                                           \
        const __half* Ab = A + (size_t)bm * K + (kc) * HBK;                     \
        const __half* Hb = W + (size_t)bn * K + (kc) * HBK;                     \
        _Pragma("unroll")                                                       \
        for (int i = 0; i < 2; i++) {                                           \
            int p = i * 256 + tid;                                              \
            int row = p >> 2, uc = p & 3;                                       \
            ua[i] = *(const uint4*)(Ab + (size_t)row * K + uc * 8);             \
            uh[i] = *(const uint4*)(Hb + (size_t)row * K + uc * 8);             \
        }                                                                       \
    }

#define HSTORE(s)                                                               \
    {                                                                           \
        char* sp = smem + (s) * HSTG;                                           \
        _Pragma("unroll")                                                       \
        for (int i = 0; i < 2; i++) {                                           \
            int p = i * 256 + tid;                                              \
            uint32_t off = (uint32_t)(p >> 2) * ASTRIDE + (uint32_t)(p & 3) * 16; \
            *(uint4*)(sp + SMH_A + off) = ua[i];                                \
            *(uint4*)(sp + SMH_W + off) = uh[i];                                \
        }                                                                       \
    }

    const int NC = K / HBK;
    HLOAD(0);
    HSTORE(0);
    __syncthreads();

    const uint32_t a_row = (uint32_t)(wm * 64) + (lane & 15);
    const uint32_t a_col = ((lane >> 4) & 1) * 16;
    const uint32_t b_row = (uint32_t)(wn * 32) + (lane & 7);
    const uint32_t b_col = ((lane >> 3) & 1) * 16;

    for (int kc = 0; kc < NC; kc++) {
        if (kc + 1 < NC) HLOAD(kc + 1);

        const uint32_t stg = sb + (uint32_t)(kc & 1) * HSTG;
#pragma unroll
        for (int s = 0; s < 2; s++) {
            uint32_t ah[4][4], wh[4][2];
            const uint32_t kb = s * 32;
#pragma unroll
            for (int mf = 0; mf < 4; mf++) {
                uint32_t ad = stg + SMH_A + (a_row + mf * 16) * ASTRIDE + kb + a_col;
                ldsm_x4(ah[mf], ad);
            }
#pragma unroll
            for (int nf = 0; nf < 4; nf++) {
                uint32_t bd = stg + SMH_W + (b_row + nf * 8) * ASTRIDE + kb + b_col;
                ldsm_x2(wh[nf], bd);
            }
#pragma unroll
            for (int mf = 0; mf < 4; mf++)
#pragma unroll
                for (int nf = 0; nf < 4; nf++)
                    mma_f16(acc[mf][nf], ah[mf], wh[nf]);
        }

        if (kc + 1 < NC) {
            HSTORE((kc + 1) & 1);
            __syncthreads();
        }
    }

    const int er = bm + wm * 64 + (lane >> 2);
    const int ec = bn + wn * 32 + (lane & 3) * 2;
#pragma unroll
    for (int mf = 0; mf < 4; mf++) {
#pragma unroll
        for (int nf = 0; nf < 4; nf++) {
            const int col = ec + nf * 8;
            const float b0 = bias[col], b1 = bias[col + 1];
#pragma unroll
            for (int h = 0; h < 2; h++) {
                const int row = er + mf * 16 + h * 8;
                float v0 = acc[mf][nf][2 * h + 0] * WUNSCALE + b0;
                float v1 = acc[mf][nf][2 * h + 1] * WUNSCALE + b1;
                const size_t go = (size_t)row * N + col;
                if (EPI == 1) {
                    float2 rv = *(const float2*)(res + go);
                    v0 += rv.x; v1 += rv.y;
                }
                if (EPI == 2) { v0 = gelu_f(v0); v1 = gelu_f(v1); }
                if (WH & 1) {
                    float2 o; o.x = v0; o.y = v1;
                    *(float2*)(C + go) = o;
                }
                if (WH & 2) {
                    __half2 hv = __floats2half2_rn(v0, v1);
                    *(__half2*)(Ch + go) = hv;
                }
            }
        }
    }
#undef HLOAD
#undef HSTORE
}

// ---------------------------------------------------------------------------
// LayerNorm (warp per row of 512); optional fp32 and fp16 outputs
// ---------------------------------------------------------------------------
__global__ void ln_kernel(const float* __restrict__ x, float* __restrict__ yf,
                          __half* __restrict__ yh,
                          const float* __restrict__ g, const float* __restrict__ b,
                          int rows)
{
    int warp = (blockIdx.x * blockDim.x + threadIdx.x) >> 5;
    int lane = threadIdx.x & 31;
    if (warp >= rows) return;
    const float* xr = x + (size_t)warp * HH;
    float v[16];
    float s = 0.0f;
#pragma unroll
    for (int i = 0; i < 16; i++) { v[i] = xr[i*32 + lane]; s += v[i]; }
#pragma unroll
    for (int o = 16; o > 0; o >>= 1) s += __shfl_xor_sync(0xffffffffu, s, o);
    float mean = s * (1.0f / HH);
    float sq = 0.0f;
#pragma unroll
    for (int i = 0; i < 16; i++) { float d = v[i] - mean; sq += d * d; }
#pragma unroll
    for (int o = 16; o > 0; o >>= 1) sq += __shfl_xor_sync(0xffffffffu, sq, o);
    float inv = rsqrtf(sq * (1.0f / HH) + 1e-5f);
#pragma unroll
    for (int i = 0; i < 16; i++) {
        int c = i*32 + lane;
        float val = (v[i] - mean) * inv * g[c] + b[c];
        if (yf) yf[(size_t)warp * HH + c] = val;
        if (yh) yh[(size_t)warp * HH + c] = __float2half_rn(val);
    }
}

// ---------------------------------------------------------------------------
// Attention (R8-winning form): one block per (b, head), 64 threads.
// fp32 Q / fused fp32 KV in global; fp32 smem; float4 inner loops; fp16 out.
// ---------------------------------------------------------------------------
__global__ __launch_bounds__(64)
void attn_kernel(const float* __restrict__ Q, const float* __restrict__ KV,
                 __half* __restrict__ O, int Tq, int Tk, const int* __restrict__ lens)
{
    __shared__ float Ks[64][64];
    __shared__ float Vs[64][64];
    __shared__ float S[64][64];

    int b = blockIdx.x >> 3;
    int h = blockIdx.x & 7;
    int t = threadIdx.x;

    const float* kbase = KV + ((size_t)b * Tk) * (2 * HH) + h * DHH;
    const float* vbase = kbase + HH;
    for (int r = 0; r < Tk; r++) {
        Ks[r][t] = kbase[(size_t)r * (2 * HH) + t];
        Vs[r][t] = vbase[(size_t)r * (2 * HH) + t];
    }
    __syncthreads();

    int limit = Tk;
    if (lens) { int l = lens[b]; limit = l < Tk ? l : Tk; }

    if (t < Tq) {
        const float* qrow = Q + ((size_t)b * Tq + t) * HH + h * DHH;
        float4 q4[16];
#pragma unroll
        for (int kk = 0; kk < 16; kk++) q4[kk] = ((const float4*)qrow)[kk];

        float mx = -1e30f;
        for (int j = 0; j < limit; j++) {
            const float4* kr = (const float4*)(&Ks[j][0]);
            float s = 0.0f;
#pragma unroll
            for (int kk = 0; kk < 16; kk++) {
                float4 k4 = kr[kk];
                s += q4[kk].x * k4.x + q4[kk].y * k4.y + q4[kk].z * k4.z + q4[kk].w * k4.w;
            }
            s *= 0.125f;
            S[j][t] = s;
            mx = fmaxf(mx, s);
        }
        float den = 0.0f;
        for (int j = 0; j < limit; j++) {
            float e = expf(S[j][t] - mx);
            S[j][t] = e; den += e;
        }
        float inv = 1.0f / den;

        float4 acc4[16];
#pragma unroll
        for (int kk = 0; kk < 16; kk++) { acc4[kk].x = acc4[kk].y = acc4[kk].z = acc4[kk].w = 0.0f; }
        for (int j = 0; j < limit; j++) {
            float p = S[j][t];
            const float4* vr = (const float4*)(&Vs[j][0]);
#pragma unroll
            for (int kk = 0; kk < 16; kk++) {
                float4 v4 = vr[kk];
                acc4[kk].x += p * v4.x; acc4[kk].y += p * v4.y;
                acc4[kk].z += p * v4.z; acc4[kk].w += p * v4.w;
            }
        }
        __half* orow = O + ((size_t)b * Tq + t) * HH + h * DHH;
#pragma unroll
        for (int kk = 0; kk < 16; kk++) {
            __half2 h01 = __floats2half2_rn(acc4[kk].x * inv, acc4[kk].y * inv);
            __half2 h23 = __floats2half2_rn(acc4[kk].z * inv, acc4[kk].w * inv);
            ((__half2*)orow)[2*kk + 0] = h01;
            ((__half2*)orow)[2*kk + 1] = h23;
        }
    }
}

// ---------------------------------------------------------------------------
// Small helpers
// ---------------------------------------------------------------------------
__global__ void small_linear(const float* __restrict__ X, const float* __restrict__ W,
                             const float* __restrict__ bias, float* __restrict__ Y,
                             int M, int N, int K)
{
    int idx = blockIdx.x * blockDim.x + threadIdx.x;
    if (idx >= M * N) return;
    int m = idx / N, n = idx % N;
    const float* xr = X + (size_t)m * K;
    const float* wr = W + (size_t)n * K;
    float acc = bias[n];
    for (int k = 0; k < K; k++) acc += xr[k] * wr[k];
    Y[idx] = acc;
}

__global__ void bcast_kernel(const float* __restrict__ src, float* __restrict__ dst,
                             int per, size_t total)
{
    for (size_t i = blockIdx.x * (size_t)blockDim.x + threadIdx.x; i < total;
         i += (size_t)gridDim.x * blockDim.x)
        dst[i] = src[i % per];
}

__global__ void build_c2_kernel(const float* __restrict__ c, const float* __restrict__ dbp,
                                float* __restrict__ out)
{
    size_t total = (size_t)BB * NI_ * HH;
    for (size_t idx = blockIdx.x * (size_t)blockDim.x + threadIdx.x; idx < total;
         idx += (size_t)gridDim.x * blockDim.x) {
        size_t col = idx % HH;
        size_t r   = (idx / HH) % NI_;
        size_t b   = idx / ((size_t)NI_ * HH);
        out[idx] = (r < CC) ? c[(b * CC + r) * HH + col] : dbp[(r - CC) * HH + col];
    }
}

__global__ void score_softmax_kernel(const float* __restrict__ qg, const float* __restrict__ P,
                                     int N, const int* __restrict__ lens,
                                     float* __restrict__ mu)
{
    __shared__ float sc[64];
    int b = blockIdx.x, t = threadIdx.x;
    float val = -1e30f;
    if (t < N) {
        bool valid = (lens == nullptr) || (t < lens[b]);
        if (valid) {
            const float* qr = qg + (size_t)b * HH;
            const float* pr = P + ((size_t)b * N + t) * HH;
            float acc = 0.0f;
            for (int k = 0; k < HH; k++) acc += qr[k] * pr[k];
            val = acc * 0.04419417382415922f;
        }
    }
    sc[t] = val;
    __syncthreads();
    float mx = -1e30f;
    for (int j = 0; j < N; j++) mx = fmaxf(mx, sc[j]);
    float sum = 0.0f;
    for (int j = 0; j < N; j++) sum += expf(sc[j] - mx);
    int stride = N + DD;
    if (t < N) mu[(size_t)b * stride + t] = expf(sc[t] - mx) / sum;
    if (t < DD) mu[(size_t)b * stride + N + t] = 1.0f / DD;
}

__global__ void build_norm_kernel(const float* __restrict__ nf, int Tn,
                                  const float* __restrict__ dbp,
                                  float* __restrict__ out, int Tall)
{
    int warp = (blockIdx.x * blockDim.x + threadIdx.x) >> 5;
    int lane = threadIdx.x & 31;
    int rows = BB * Tall;
    if (warp >= rows) return;
    int b = warp / Tall, r = warp % Tall;
    const float* src = (r < Tn) ? nf + ((size_t)b * Tn + r) * HH : dbp + (size_t)(r - Tn) * HH;
    float v[16];
    float sq = 0.0f;
#pragma unroll
    for (int i = 0; i < 16; i++) { v[i] = src[i*32 + lane]; sq += v[i]*v[i]; }
#pragma unroll
    for (int o = 16; o > 0; o >>= 1) sq += __shfl_xor_sync(0xffffffffu, sq, o);
    float inv = 1.0f / fmaxf(sqrtf(sq), 1e-12f);
    float* dst = out + (size_t)warp * HH;
#pragma unroll
    for (int i = 0; i < 16; i++) dst[i*32 + lane] = v[i] * inv;
}

__global__ void sim_kernel(const float* __restrict__ Ai, const float* __restrict__ At,
                           float* __restrict__ sim)
{
    int b = blockIdx.x;
    const float4* ab = (const float4*)(Ai + (size_t)b * 40 * HH);
    const float4* tb = (const float4*)(At + (size_t)b * 68 * HH);
    for (int p = threadIdx.x; p < 40 * 68; p += blockDim.x) {
        int i = p / 68, j = p % 68;
        const float4* ar = ab + i * (HH/4);
        const float4* tr = tb + j * (HH/4);
        float acc = 0.0f;
        for (int k = 0; k < HH/4; k++) {
            float4 a = ar[k], t = tr[k];
            acc += a.x*t.x + a.y*t.y + a.z*t.z + a.w*t.w;
        }
        sim[((size_t)b * 40 + i) * 68 + j] = acc;
    }
}

__global__ __launch_bounds__(128)
void sinkhorn_kernel(const float* __restrict__ sim, const float* __restrict__ mu,
                     const float* __restrict__ mv, float* __restrict__ out)
{
    __shared__ float Km[40*68];
    __shared__ float Sm[40*68];
    __shared__ float u[40], v[68], muS[40], mvS[68], red[128];
    int b = blockIdx.x, t = threadIdx.x;

    for (int p = t; p < 40*68; p += 128) {
        float s = sim[(size_t)b * 40*68 + p];
        Sm[p] = s;
        Km[p] = expf((s - 1.0f) * 10.0f);
    }
    if (t < 40) muS[t] = mu[(size_t)b*40 + t];
    if (t < 68) { mvS[t] = mv[(size_t)b*68 + t]; v[t] = 1.0f; }
    __syncthreads();

    for (int it = 0; it < 10; it++) {
        if (t < 40) {
            float s = 0.0f;
            for (int j = 0; j < 68; j++) s += Km[t*68 + j] * v[j];
            u[t] = muS[t] / s;
        }
        __syncthreads();
        if (t < 68) {
            float s = 0.0f;
            for (int i = 0; i < 40; i++) s += Km[i*68 + t] * u[i];
            v[t] = mvS[t] / s;
        }
        __syncthreads();
    }

    float acc = 0.0f;
    for (int p = t; p < NI_*NT_; p += 128) {
        int i = p / NT_, j = p % NT_;
        float k = Km[i*68 + j];
        acc += u[i] * k * v[j] * Sm[i*68 + j];
    }
    red[t] = acc;
    __syncthreads();
    for (int o = 64; o > 0; o >>= 1) {
        if (t < o) red[t] += red[t + o];
        __syncthreads();
    }
    if (t == 0) out[b] = red[0];
}

// ---------------------------------------------------------------------------
// Host-side helpers
// ---------------------------------------------------------------------------
static inline void gemm(cudaStream_t st, int epi, int wh, const __half* A,
                        const __half* W,
                        const float* bias, const float* res, float* C, __half* Ch,
                        int M, int N, int K)
{
    dim3 grid(N / 128, M / 128);
    if (epi == 0 && wh == 1)
        hgemm_kernel<0,1><<<grid, 256, HSMEM, st>>>(A, W, bias, res, C, Ch, M, N, K);
    else if (epi == 0 && wh == 3)
        hgemm_kernel<0,3><<<grid, 256, HSMEM, st>>>(A, W, bias, res, C, Ch, M, N, K);
    else if (epi == 1)
        hgemm_kernel<1,1><<<grid, 256, HSMEM, st>>>(A, W, bias, res, C, Ch, M, N, K);
    else
        hgemm_kernel<2,2><<<grid, 256, HSMEM, st>>>(A, W, bias, res, C, Ch, M, N, K);
}

static inline void ln_run(cudaStream_t st, const float* x, float* yf, __half* yh,
                          const float* g, const float* b, int rows)
{
    int blocks = (rows + 7) / 8;
    ln_kernel<<<blocks, 256, 0, st>>>(x, yf, yh, g, b, rows);
}

struct Params {
    const float *attn_in_b, *attn_out_b, *ff1_b, *ff2_b, *lln_g, *lln_b;
    const int* lengths;
    float* base;
    __half* hb;
    __half* wb;
};

static void xlayer(const Params& P, cudaStream_t st, int lane,
                   const float* src, int Ts, float* tgt, int Tt,
                   int s, int l, bool masked)
{
    float* base = P.base;
    __half* hl = P.hb + HB_LANE + (size_t)lane * LANE_H;
    __half* wb = P.wb;
    __half* h_tgtln = hl + HL_TGT;
    __half* h_srcln = hl + HL_SRC;
    __half* h_ao    = hl + HL_AO;
    __half* h_hid   = hl + HL_HID;
    float* p_q  = base + O_LANEF + (size_t)lane * LANE_F + OL_Q;
    float* p_kv = base + O_LANEF + (size_t)lane * LANE_F + OL_KV;

    const int Mt = BB * Tt, Ms = BB * Ts;
    const int sl = s * LL + l;
    const float* lg = P.lln_g + (size_t)sl * 3 * HH;
    const float* lb = P.lln_b + (size_t)sl * 3 * HH;
    const float* ib = P.attn_in_b  + (size_t)sl * 3 * HH;
    const float* ob = P.attn_out_b + (size_t)sl * HH;
    const float* f1b = P.ff1_b + (size_t)sl * 4 * HH;
    const float* f2b = P.ff2_b + (size_t)sl * HH;

    __half* ain  = wb + WO_AIN  + (size_t)sl * 3 * HH * HH;
    __half* aout = wb + WO_AOUT + (size_t)sl * HH * HH;
    __half* f1   = wb + WO_FF1  + (size_t)sl * 4 * HH * HH;
    __half* f2   = wb + WO_FF2  + (size_t)sl * 4 * HH * HH;

    ln_run(st, src, nullptr, h_srcln, lg + 0*HH, lb + 0*HH, Ms);
    ln_run(st, tgt, nullptr, h_tgtln, lg + 1*HH, lb + 1*HH, Mt);
    gemm(st, 0, 1, h_tgtln, ain, ib, nullptr, p_q, nullptr, Mt, HH, HH);
    gemm(st, 0, 1, h_srcln, ain + (size_t)HH*HH, ib + HH,
         nullptr, p_kv, nullptr, Ms, 2*HH, HH);
    attn_kernel<<<BB * NHH, 64, 0, st>>>(p_q, p_kv, h_ao, Tt, Ts,
                                         masked ? P.lengths : nullptr);
    gemm(st, 1, 1, h_ao, aout, ob, tgt, tgt, nullptr, Mt, HH, HH);
    ln_run(st, tgt, nullptr, h_tgtln, lg + 2*HH, lb + 2*HH, Mt);
    gemm(st, 2, 2, h_tgtln, f1, f1b, nullptr, nullptr, h_hid, Mt, 4*HH, HH);
    gemm(st, 1, 1, h_hid, f2, f2b, tgt, tgt, nullptr, Mt, HH, 4*HH);
}

// ---------------------------------------------------------------------------
// kernel_launch
// ---------------------------------------------------------------------------
extern "C" void kernel_launch(void* const* d_in, const int* in_sizes, int n_in,
                              void* d_out, int out_size)
{
    const float* img_global   = (const float*)d_in[0];
    const float* img_nodes    = (const float*)d_in[1];
    const float* txt_global   = (const float*)d_in[2];
    const float* txt_nodes    = (const float*)d_in[3];
    const int*   lengths      = (const int*)  d_in[4];
    const float* img_in_w     = (const float*)d_in[5];
    const float* img_in_b     = (const float*)d_in[6];
    const float* txt_in_w     = (const float*)d_in[7];
    const float* txt_in_b     = (const float*)d_in[8];
    const float* img_concepts = (const float*)d_in[9];
    const float* txt_concepts = (const float*)d_in[10];
    const float* img_dustbins = (const float*)d_in[11];
    const float* txt_dustbins = (const float*)d_in[12];
    const float* ln_g         = (const float*)d_in[13];
    const float* ln_b         = (const float*)d_in[14];
    const float* attn_in_w    = (const float*)d_in[15];
    const float* attn_in_b    = (const float*)d_in[16];
    const float* attn_out_w   = (const float*)d_in[17];
    const float* attn_out_b   = (const float*)d_in[18];
    const float* ff1_w        = (const float*)d_in[19];
    const float* ff1_b        = (const float*)d_in[20];
    const float* ff2_w        = (const float*)d_in[21];
    const float* ff2_b        = (const float*)d_in[22];
    const float* lln_g        = (const float*)d_in[23];
    const float* lln_b        = (const float*)d_in[24];
    const float* db_w         = (const float*)d_in[25];
    const float* db_b         = (const float*)d_in[26];
    const float* proj_w       = (const float*)d_in[27];
    const float* proj_b       = (const float*)d_in[28];
    const float* qg_w         = (const float*)d_in[29];
    const float* qg_b         = (const float*)d_in[30];
    float* out = (float*)d_out;

    cudaFuncSetAttribute(hgemm_kernel<0,1>, cudaFuncAttributeMaxDynamicSharedMemorySize, HSMEM);
    cudaFuncSetAttribute(hgemm_kernel<0,3>, cudaFuncAttributeMaxDynamicSharedMemorySize, HSMEM);
    cudaFuncSetAttribute(hgemm_kernel<1,1>, cudaFuncAttributeMaxDynamicSharedMemorySize, HSMEM);
    cudaFuncSetAttribute(hgemm_kernel<2,2>, cudaFuncAttributeMaxDynamicSharedMemorySize, HSMEM);

    float* base = nullptr;
    cudaGetSymbolAddress((void**)&base, g_buf);
    __half* hb = nullptr;
    cudaGetSymbolAddress((void**)&hb, g_hbuf);
    __half* wb = nullptr;
    cudaGetSymbolAddress((void**)&wb, g_wbuf);

    // --- streams & events (created per call; host handles intentionally leaked:
    // kernel_launch runs only for correctness + capture, never per-replay) ---
    cudaStream_t sA = 0;            // legacy default stream (the captured one)
    cudaStream_t sB;
    cudaStreamCreateWithFlags(&sB, cudaStreamNonBlocking);
    cudaEvent_t evs[64];
    for (int i = 0; i < 64; i++) cudaEventCreateWithFlags(&evs[i], cudaEventDisableTiming);
    int evi = 0;
    auto forkto = [&](cudaStream_t to, cudaStream_t from) {
        cudaEventRecord(evs[evi], from);
        cudaStreamWaitEvent(to, evs[evi], 0);
        evi++;
    };
    auto joinAB = [&]() { forkto(sB, sA); forkto(sA, sB); };

    float* p_imgn  = base + O_IMGN;
    float* p_txtn  = base + O_TXTN;
    float* p_imgc  = base + O_IMGC;
    float* p_txtc  = base + O_TXTC;
    float* p_c2a   = base + O_C2A;
    float* p_c2b   = base + O_C2B;
    float* p_imgnf = base + O_IMGNF;
    float* p_txtnf = base + O_TXTNF;
    float* p_p2    = base + O_P2;
    float* p_p3    = base + O_P3;
    float* p_qi    = base + O_QI;
    float* p_qt    = base + O_QT;
    float* p_alli  = base + O_ALLI;
    float* p_allt  = base + O_ALLT;
    float* p_sim   = base + O_SIM;
    float* p_mu    = base + O_MU;
    float* p_mv    = base + O_MV;
    float* p_cn0   = base + O_CN0;
    float* p_cn1   = base + O_CN1;
    float* p_db0   = base + O_DB0;
    float* p_db1   = base + O_DB1;
    float* p_dbp   = base + O_DBP;
    float* p_dbp2  = base + O_DBP2;
    float* p_tmpA  = base + O_LANEF + OL_Q;             // lane0 Q as fp32 tmp
    float* p_tmpB  = base + O_LANEF + LANE_F + OL_Q;    // lane1 Q as fp32 tmp
    __half* hl0 = hb + HB_LANE;
    __half* hl1 = hb + HB_LANE + LANE_H;

    // fork B off the origin before any B work
    forkto(sB, sA);

    // --- weight/input conversion, split across streams ---
    wconv_kernel<<<1024, 256, 0, sA>>>(img_in_w,   wb + WO_IMGIN, SZ_IMGIN/4);
    wconv_kernel<<<2048, 256, 0, sA>>>(attn_in_w,  wb + WO_AIN,   SZ_AIN/4);
    wconv_kernel<<<2048, 256, 0, sA>>>(ff1_w,      wb + WO_FF1,   SZ_FF1/4);
    wconv_kernel<<<1024, 256, 0, sA>>>(proj_w,     wb + WO_PROJ,  SZ_PROJ/4);
    aconv_kernel<<<2048, 256, 0, sA>>>(img_nodes,  hb + HB_INI, (size_t)BB*NI_*DI_/4);
    aconv_kernel<<<512,  256, 0, sA>>>(img_global, hb + HB_GI,  (size_t)BB*GG/4);
    ln_run(sA, img_concepts, p_cn0, nullptr, ln_g + 4*HH, ln_b + 4*HH, CC);
    ln_run(sA, img_dustbins, p_db0, nullptr, ln_g + 6*HH, ln_b + 6*HH, DD);
    bcast_kernel<<<2048, 256, 0, sA>>>(p_cn0, p_imgc, CC*HH, (size_t)BB*CC*HH);

    wconv_kernel<<<1024, 256, 0, sB>>>(txt_in_w,   wb + WO_TXTIN, SZ_TXTIN/4);
    wconv_kernel<<<1024, 256, 0, sB>>>(attn_out_w, wb + WO_AOUT,  SZ_AOUT/4);
    wconv_kernel<<<2048, 256, 0, sB>>>(ff2_w,      wb + WO_FF2,   SZ_FF2/4);
    wconv_kernel<<<1024, 256, 0, sB>>>(qg_w,       wb + WO_QG,    SZ_QG/4);
    aconv_kernel<<<2048, 256, 0, sB>>>(txt_nodes,  hb + HB_INT, (size_t)BB*NT_*DT_/4);
    aconv_kernel<<<512,  256, 0, sB>>>(txt_global, hb + HB_GT,  (size_t)BB*GG/4);
    ln_run(sB, txt_concepts, p_cn1, nullptr, ln_g + 5*HH, ln_b + 5*HH, CC);
    ln_run(sB, txt_dustbins, p_db1, nullptr, ln_g + 7*HH, ln_b + 7*HH, DD);
    bcast_kernel<<<2048, 256, 0, sB>>>(p_cn1, p_txtc, CC*HH, (size_t)BB*CC*HH);

    // --- input projections + LN (A: img, B: txt) ---
    gemm(sA, 0, 1, hb + HB_INI, wb + WO_IMGIN, img_in_b,
         nullptr, p_tmpA, nullptr, BB*NI_, HH, DI_);
    ln_run(sA, p_tmpA, p_imgn, nullptr, ln_g + 0*HH, ln_b + 0*HH, BB*NI_);
    gemm(sB, 0, 1, hb + HB_INT, wb + WO_TXTIN, txt_in_b,
         nullptr, p_tmpB, nullptr, BB*NT_, HH, DT_);
    ln_run(sB, p_tmpB, p_txtn, nullptr, ln_g + 1*HH, ln_b + 1*HH, BB*NT_);

    Params P{attn_in_b, attn_out_b, ff1_b, ff2_b, lln_g, lln_b, lengths, base, hb, wb};

    // --- layers (A: img-side, B: txt-side; joins at true dependency points) ---
    for (int l = 0; l < LL; l++) {
        joinAB();
        xlayer(P, sA, 0, p_imgn, NI_, p_imgc, CC, 0, l, false);
        small_linear<<<(DD*HH + 255)/256, 256, 0, sA>>>(p_db0, db_w + (size_t)(0*LL + l)*HH*HH,
                                                        db_b + (size_t)(0*LL + l)*HH, p_dbp, DD, HH, HH);
        build_c2_kernel<<<4096, 256, 0, sA>>>(p_imgc, p_dbp, p_c2a);

        xlayer(P, sB, 1, p_txtn, NT_, p_txtc, CC, 1, l, true);
        small_linear<<<(DD*HH + 255)/256, 256, 0, sB>>>(p_db1, db_w + (size_t)(1*LL + l)*HH*HH,
                                                        db_b + (size_t)(1*LL + l)*HH, p_dbp2, DD, HH, HH);
        build_c2_kernel<<<4096, 256, 0, sB>>>(p_txtc, p_dbp2, p_c2b);

        joinAB();
        xlayer(P, sA, 0, p_c2a, NI_, p_txtn, NT_, 2, l, false);
        xlayer(P, sB, 1, p_c2b, NI_, p_imgn, NI_, 3, l, false);
    }
    joinAB();

    // --- tail (A: img-side, B: txt-side) ---
    __half* proj = wb + WO_PROJ;

    ln_run(sA, p_imgn, nullptr, hl0 + HL_SRC, ln_g + 2*HH, ln_b + 2*HH, BB*NI_);
    gemm(sA, 0, 3, hl0 + HL_SRC, proj, proj_b, nullptr,
         p_imgnf, hb + HB_IMGNF, BB*NI_, HH, HH);
    gemm(sA, 0, 1, hb + HB_IMGNF, proj + 2*(size_t)HH*HH,
         proj_b + 2*HH, nullptr, p_p2, nullptr, BB*NI_, HH, HH);
    gemm(sA, 0, 1, hb + HB_GI, wb + WO_QG, qg_b,
         nullptr, p_qi, nullptr, BB, HH, GG);
    score_softmax_kernel<<<BB, 64, 0, sA>>>(p_qi, p_p2, NI_, nullptr, p_mu);
    small_linear<<<(DD*HH + 255)/256, 256, 0, sA>>>(p_db0, proj_w + 4*(size_t)HH*HH,
                                                    proj_b + 4*HH, p_dbp, DD, HH, HH);
    build_norm_kernel<<<(BB*40*32 + 255)/256, 256, 0, sA>>>(p_imgnf, NI_, p_dbp, p_alli, 40);

    ln_run(sB, p_txtn, nullptr, hl1 + HL_SRC, ln_g + 3*HH, ln_b + 3*HH, BB*NT_);
    gemm(sB, 0, 3, hl1 + HL_SRC, proj + (size_t)HH*HH,
         proj_b + HH, nullptr, p_txtnf, hb + HB_TXTNF, BB*NT_, HH, HH);
    gemm(sB, 0, 1, hb + HB_TXTNF, proj + 3*(size_t)HH*HH,
         proj_b + 3*HH, nullptr, p_p3, nullptr, BB*NT_, HH, HH);
    gemm(sB, 0, 1, hb + HB_GT, wb + WO_QG + (size_t)HH*GG,
         qg_b + HH, nullptr, p_qt, nullptr, BB, HH, GG);
    score_softmax_kernel<<<BB, 64, 0, sB>>>(p_qt, p_p3, NT_, lengths, p_mv);
    small_linear<<<(DD*HH + 255)/256, 256, 0, sB>>>(p_db1, proj_w + 5*(size_t)HH*HH,
                                                    proj_b + 5*HH, p_dbp2, DD, HH, HH);
    build_norm_kernel<<<(BB*68*32 + 255)/256, 256, 0, sB>>>(p_txtnf, NT_, p_dbp2, p_allt, 68);

    // join B back into origin, finish on A
    forkto(sA, sB);
    sim_kernel<<<BB, 256, 0, sA>>>(p_alli, p_allt, p_sim);
    sinkhorn_kernel<<<BB, 128, 0, sA>>>(p_sim, p_mu, p_mv, out);
}

// round 14
// speedup vs baseline: 1.2775x; 1.0567x over previous
#include <cuda_runtime.h>
#include <cuda_fp16.h>
#include <math.h>
#include <stdint.h>

// ---------------------------------------------------------------------------
// Problem constants
// ---------------------------------------------------------------------------
#define BB   512
#define NI_  36
#define NT_  64
#define DI_  2048
#define DT_  768
#define GG   1024
#define HH   512
#define CC   32
#define DD   4
#define LL   2
#define NHH  8
#define DHH  64

constexpr size_t UU = (size_t)BB * NT_ * HH;   // 16.78M elements, the unit tile

// ---------------------------------------------------------------------------
// fp32 scratch (lane0/lane1 get private Q/KV blocks)
// ---------------------------------------------------------------------------
constexpr size_t O_IMGN  = 0;
constexpr size_t O_TXTN  = O_IMGN  + (size_t)BB*NI_*HH;
constexpr size_t O_IMGC  = O_TXTN  + UU;
constexpr size_t O_TXTC  = O_IMGC  + (size_t)BB*CC*HH;
constexpr size_t O_LANEF = O_TXTC  + (size_t)BB*CC*HH;   // 2 lanes x (Q + KV)
constexpr size_t LANE_F  = 3 * UU;                        // Q (1U) + KV (2U)
constexpr size_t OL_Q    = 0;
constexpr size_t OL_KV   = UU;
constexpr size_t O_C2A   = O_LANEF + 2 * LANE_F;
constexpr size_t O_C2B   = O_C2A   + (size_t)BB*NI_*HH;
constexpr size_t O_IMGNF = O_C2B   + (size_t)BB*NI_*HH;
constexpr size_t O_TXTNF = O_IMGNF + (size_t)BB*NI_*HH;
constexpr size_t O_P2    = O_TXTNF + UU;
constexpr size_t O_P3    = O_P2    + (size_t)BB*NI_*HH;
constexpr size_t O_QI    = O_P3    + UU;
constexpr size_t O_QT    = O_QI    + (size_t)BB*HH;
constexpr size_t O_ALLI  = O_QT    + (size_t)BB*HH;
constexpr size_t O_ALLT  = O_ALLI  + (size_t)BB*40*HH;
constexpr size_t O_SIM   = O_ALLT  + (size_t)BB*68*HH;
constexpr size_t O_MU    = O_SIM   + (size_t)BB*40*68;
constexpr size_t O_MV    = O_MU    + (size_t)BB*40;
constexpr size_t O_CN0   = O_MV    + (size_t)BB*68;
constexpr size_t O_CN1   = O_CN0   + (size_t)CC*HH;
constexpr size_t O_DB0   = O_CN1   + (size_t)CC*HH;
constexpr size_t O_DB1   = O_DB0   + (size_t)DD*HH;
constexpr size_t O_DBP   = O_DB1   + (size_t)DD*HH;
constexpr size_t O_DBP2  = O_DBP   + (size_t)DD*HH;
constexpr size_t TOTAL_F = O_DBP2  + (size_t)DD*HH;
__device__ __align__(256) float g_buf[TOTAL_F];

// ---------------------------------------------------------------------------
// fp16 activation scratch (lane-private xlayer blocks + shared tail blocks)
// ---------------------------------------------------------------------------
constexpr size_t LANE_H   = 7 * UU;            // TGT + SRC + AO + HID(4U)
constexpr size_t HL_TGT   = 0;
constexpr size_t HL_SRC   = UU;
constexpr size_t HL_AO    = 2 * UU;
constexpr size_t HL_HID   = 3 * UU;
constexpr size_t HB_LANE  = 0;
constexpr size_t HB_INI   = HB_LANE + 2 * LANE_H;
constexpr size_t HB_INT   = HB_INI  + (size_t)BB*NI_*DI_;
constexpr size_t HB_GI    = HB_INT  + (size_t)BB*NT_*DT_;
constexpr size_t HB_GT    = HB_GI   + (size_t)BB*GG;
constexpr size_t HB_IMGNF = HB_GT   + (size_t)BB*GG;
constexpr size_t HB_TXTNF = HB_IMGNF + (size_t)BB*NI_*HH;
constexpr size_t TOTAL_H  = HB_TXTNF + UU;
__device__ __align__(256) __half g_hbuf[TOTAL_H];

// ---------------------------------------------------------------------------
// fp16 weight scratch (single term, weights pre-scaled by 64)
// ---------------------------------------------------------------------------
constexpr size_t SZ_IMGIN = (size_t)HH*DI_;
constexpr size_t SZ_TXTIN = (size_t)HH*DT_;
constexpr size_t SZ_AIN   = (size_t)8*3*HH*HH;
constexpr size_t SZ_AOUT  = (size_t)8*HH*HH;
constexpr size_t SZ_FF1   = (size_t)8*4*HH*HH;
constexpr size_t SZ_FF2   = (size_t)8*4*HH*HH;
constexpr size_t SZ_PROJ  = (size_t)6*HH*HH;
constexpr size_t SZ_QG    = (size_t)2*HH*GG;
constexpr size_t WO_IMGIN = 0;
constexpr size_t WO_TXTIN = WO_IMGIN + SZ_IMGIN;
constexpr size_t WO_AIN   = WO_TXTIN + SZ_TXTIN;
constexpr size_t WO_AOUT  = WO_AIN   + SZ_AIN;
constexpr size_t WO_FF1   = WO_AOUT  + SZ_AOUT;
constexpr size_t WO_FF2   = WO_FF1   + SZ_FF1;
constexpr size_t WO_PROJ  = WO_FF2   + SZ_FF2;
constexpr size_t WO_QG    = WO_PROJ  + SZ_PROJ;
constexpr size_t TOTAL_W  = WO_QG    + SZ_QG;
__device__ __align__(256) __half g_wbuf[TOTAL_W];

#define WSCALE   64.0f
#define WUNSCALE 0.015625f

// ---------------------------------------------------------------------------
// PTX helpers (sm_80-era only)
// ---------------------------------------------------------------------------
__device__ __forceinline__ uint32_t s2u(const void* p) {
    uint32_t a;
    asm("{ .reg .u64 t; cvta.to.shared.u64 t, %1; cvt.u32.u64 %0, t; }"
        : "=r"(a) : "l"(p));
    return a;
}
__device__ __forceinline__ void ldsm_x4(uint32_t* r, uint32_t addr) {
    asm volatile("ldmatrix.sync.aligned.m8n8.x4.shared.b16 {%0,%1,%2,%3}, [%4];"
                 : "=r"(r[0]), "=r"(r[1]), "=r"(r[2]), "=r"(r[3]) : "r"(addr));
}
__device__ __forceinline__ void ldsm_x2(uint32_t* r, uint32_t addr) {
    asm volatile("ldmatrix.sync.aligned.m8n8.x2.shared.b16 {%0,%1}, [%2];"
                 : "=r"(r[0]), "=r"(r[1]) : "r"(addr));
}
__device__ __forceinline__ void mma_f16(float* c, const uint32_t* a, const uint32_t* b) {
    asm volatile(
        "mma.sync.aligned.m16n8k16.row.col.f32.f16.f16.f32 "
        "{%0,%1,%2,%3}, {%4,%5,%6,%7}, {%8,%9}, {%0,%1,%2,%3};"
        : "+f"(c[0]), "+f"(c[1]), "+f"(c[2]), "+f"(c[3])
        : "r"(a[0]), "r"(a[1]), "r"(a[2]), "r"(a[3]), "r"(b[0]), "r"(b[1]));
}
__device__ __forceinline__ void cpa16(uint32_t saddr, const void* g) {
    asm volatile("cp.async.cg.shared.global [%0], [%1], 16;"
                 :: "r"(saddr), "l"(g) : "memory");
}
__device__ __forceinline__ float gelu_f(float x) {
    return 0.5f * x * (1.0f + erff(x * 0.7071067811865476f));
}

// ---------------------------------------------------------------------------
// Conversion kernels
// ---------------------------------------------------------------------------
__global__ void wconv_kernel(const float* __restrict__ w, __half* __restrict__ hi,
                             size_t n4)
{
    for (size_t i = blockIdx.x * (size_t)blockDim.x + threadIdx.x; i < n4;
         i += (size_t)gridDim.x * blockDim.x) {
        float4 f = reinterpret_cast<const float4*>(w)[i];
        __half2 H01 = __floats2half2_rn(f.x * WSCALE, f.y * WSCALE);
        __half2 H23 = __floats2half2_rn(f.z * WSCALE, f.w * WSCALE);
        uint2 Hv;
        Hv.x = *reinterpret_cast<uint32_t*>(&H01);
        Hv.y = *reinterpret_cast<uint32_t*>(&H23);
        reinterpret_cast<uint2*>(hi)[i] = Hv;
    }
}

__global__ void aconv_kernel(const float* __restrict__ x, __half* __restrict__ y, size_t n4)
{
    for (size_t i = blockIdx.x * (size_t)blockDim.x + threadIdx.x; i < n4;
         i += (size_t)gridDim.x * blockDim.x) {
        float4 f = reinterpret_cast<const float4*>(x)[i];
        __half2 a = __floats2half2_rn(f.x, f.y);
        __half2 b = __floats2half2_rn(f.z, f.w);
        uint2 o;
        o.x = *reinterpret_cast<uint32_t*>(&a);
        o.y = *reinterpret_cast<uint32_t*>(&b);
        reinterpret_cast<uint2*>(y)[i] = o;
    }
}

// ---------------------------------------------------------------------------
// fp16 tensor-core GEMM (single term): C = A @ W^T * 2^-6 + bias (+res/gelu)
// WH: bit0 write fp32 C, bit1 write fp16 Ch.  2 CTAs/SM; 4-stage cp.async ring.
// ---------------------------------------------------------------------------
#define HBK 32
#define ASTRIDE 80
#define SMH_A   0
#define SMH_W   10240
#define HSTG    20480
#define HSMEM   (4*HSTG)     // 81920 bytes; x2 CTAs = 160KB <= 228KB

template<int EPI, int WH>
__global__ __launch_bounds__(256, 2)
void hgemm_kernel(const __half* __restrict__ A, const __half* __restrict__ W,
                  const float* __restrict__ bias, const float* __restrict__ res,
                  float* __restrict__ C, __half* __restrict__ Ch,
                  int M, int N, int K)
{
    extern __shared__ __align__(16) char smem[];
    const uint32_t sb = s2u(smem);
    const int tid  = threadIdx.x;
    const int bm   = blockIdx.y * 128;
    const int bn   = blockIdx.x * 128;
    const int wid  = tid >> 5;
    const int lane = tid & 31;
    const int wm   = wid >> 2;
    const int wn   = wid & 3;

    float acc[4][4][4];
#pragma unroll
    for (int i = 0; i < 4; i++)
#pragma unroll
        for (int j = 0; j < 4; j++)
#pragma unroll
            for (int k = 0; k < 4; k++) acc[i][j][k] = 0.0f;

    // per-thread copy coordinates (2 x 16B for A, 2 x 16B for W per chunk)
    const int p0 = tid, p1 = 256 + tid;
    const int r0 = p0 >> 2, c0 = p0 & 3;
    const int r1 = p1 >> 2, c1 = p1 & 3;
    const uint32_t so0 = (uint32_t)r0 * ASTRIDE + (uint32_t)c0 * 16;
    const uint32_t so1 = (uint32_t)r1 * ASTRIDE + (uint32_t)c1 * 16;

#define HISSUE(kc, s)                                                           \
    {                                                                           \
        const __half* Ab = A + (size_t)bm * K + (kc) * HBK;                     \
        const __half* Hb = W + (size_t)bn * K + (kc) * HBK;                     \
        const uint32_t sp = sb + (uint32_t)(s) * HSTG;                          \
        cpa16(sp + SMH_A + so0, Ab + (size_t)r0 * K + c0 * 8);                  \
        cpa16(sp + SMH_A + so1, Ab + (size_t)r1 * K + c1 * 8);                  \
        cpa16(sp + SMH_W + so0, Hb + (size_t)r0 * K + c0 * 8);                  \
        cpa16(sp + SMH_W + so1, Hb + (size_t)r1 * K + c1 * 8);                  \
        asm volatile("cp.async.commit_group;" ::: "memory");                    \
    }

    const int NC = K / HBK;
    HISSUE(0, 0);
    if (NC > 1) HISSUE(1, 1);
    if (NC > 2) HISSUE(2, 2);

    const uint32_t a_row = (uint32_t)(wm * 64) + (lane & 15);
    const uint32_t a_col = ((lane >> 4) & 1) * 16;
    const uint32_t b_row = (uint32_t)(wn * 32) + (lane & 7);
    const uint32_t b_col = ((lane >> 3) & 1) * 16;

    for (int kc = 0; kc < NC; kc++) {
        // chunk kc complete when pending groups <= (#chunks issued beyond kc)
        if (kc + 2 < NC)
            asm volatile("cp.async.wait_group 2;" ::: "memory");
        else if (kc + 1 < NC)
            asm volatile("cp.async.wait_group 1;" ::: "memory");
        else
            asm volatile("cp.async.wait_group 0;" ::: "memory");
        __syncthreads();   // chunk kc visible; all threads done reading buf (kc-1)%4

        if (kc + 3 < NC) HISSUE(kc + 3, (kc + 3) & 3);

        const uint32_t stg = sb + (uint32_t)(kc & 3) * HSTG;
#pragma unroll
        for (int s = 0; s < 2; s++) {
            uint32_t ah[4][4], wh[4][2];
            const uint32_t kb = s * 32;
#pragma unroll
            for (int mf = 0; mf < 4; mf++) {
                uint32_t ad = stg + SMH_A + (a_row + mf * 16) * ASTRIDE + kb + a_col;
                ldsm_x4(ah[mf], ad);
            }
#pragma unroll
            for (int nf = 0; nf < 4; nf++) {
                uint32_t bd = stg + SMH_W + (b_row + nf * 8) * ASTRIDE + kb + b_col;
                ldsm_x2(wh[nf], bd);
            }
#pragma unroll
            for (int mf = 0; mf < 4; mf++)
#pragma unroll
                for (int nf = 0; nf < 4; nf++)
                    mma_f16(acc[mf][nf], ah[mf], wh[nf]);
        }
    }

    const int er = bm + wm * 64 + (lane >> 2);
    const int ec = bn + wn * 32 + (lane & 3) * 2;
#pragma unroll
    for (int mf = 0; mf < 4; mf++) {
#pragma unroll
        for (int nf = 0; nf < 4; nf++) {
            const int col = ec + nf * 8;
            const float b0 = bias[col], b1 = bias[col + 1];
#pragma unroll
            for (int h = 0; h < 2; h++) {
                const int row = er + mf * 16 + h * 8;
                float v0 = acc[mf][nf][2 * h + 0] * WUNSCALE + b0;
                float v1 = acc[mf][nf][2 * h + 1] * WUNSCALE + b1;
                const size_t go = (size_t)row * N + col;
                if (EPI == 1) {
                    float2 rv = *(const float2*)(res + go);
                    v0 += rv.x; v1 += rv.y;
                }
                if (EPI == 2) { v0 = gelu_f(v0); v1 = gelu_f(v1); }
                if (WH & 1) {
                    float2 o; o.x = v0; o.y = v1;
                    *(float2*)(C + go) = o;
                }
                if (WH & 2) {
                    __half2 hv = __floats2half2_rn(v0, v1);
                    *(__half2*)(Ch + go) = hv;
                }
            }
        }
    }
#undef HISSUE
}

// ---------------------------------------------------------------------------
// LayerNorm (warp per row of 512); optional fp32 and fp16 outputs
// ---------------------------------------------------------------------------
__global__ void ln_kernel(const float* __restrict__ x, float* __restrict__ yf,
                          __half* __restrict__ yh,
                          const float* __restrict__ g, const float* __restrict__ b,
                          int rows)
{
    int warp = (blockIdx.x * blockDim.x + threadIdx.x) >> 5;
    int lane = threadIdx.x & 31;
    if (warp >= rows) return;
    const float* xr = x + (size_t)warp * HH;
    float v[16];
    float s = 0.0f;
#pragma unroll
    for (int i = 0; i < 16; i++) { v[i] = xr[i*32 + lane]; s += v[i]; }
#pragma unroll
    for (int o = 16; o > 0; o >>= 1) s += __shfl_xor_sync(0xffffffffu, s, o);
    float mean = s * (1.0f / HH);
    float sq = 0.0f;
#pragma unroll
    for (int i = 0; i < 16; i++) { float d = v[i] - mean; sq += d * d; }
#pragma unroll
    for (int o = 16; o > 0; o >>= 1) sq += __shfl_xor_sync(0xffffffffu, sq, o);
    float inv = rsqrtf(sq * (1.0f / HH) + 1e-5f);
#pragma unroll
    for (int i = 0; i < 16; i++) {
        int c = i*32 + lane;
        float val = (v[i] - mean) * inv * g[c] + b[c];
        if (yf) yf[(size_t)warp * HH + c] = val;
        if (yh) yh[(size_t)warp * HH + c] = __float2half_rn(val);
    }
}

// ---------------------------------------------------------------------------
// Attention (R8-winning form): one block per (b, head), 64 threads.
// fp32 Q / fused fp32 KV in global; fp32 smem; float4 inner loops; fp16 out.
// ---------------------------------------------------------------------------
__global__ __launch_bounds__(64)
void attn_kernel(const float* __restrict__ Q, const float* __restrict__ KV,
                 __half* __restrict__ O, int Tq, int Tk, const int* __restrict__ lens)
{
    __shared__ float Ks[64][64];
    __shared__ float Vs[64][64];
    __shared__ float S[64][64];

    int b = blockIdx.x >> 3;
    int h = blockIdx.x & 7;
    int t = threadIdx.x;

    const float* kbase = KV + ((size_t)b * Tk) * (2 * HH) + h * DHH;
    const float* vbase = kbase + HH;
    for (int r = 0; r < Tk; r++) {
        Ks[r][t] = kbase[(size_t)r * (2 * HH) + t];
        Vs[r][t] = vbase[(size_t)r * (2 * HH) + t];
    }
    __syncthreads();

    int limit = Tk;
    if (lens) { int l = lens[b]; limit = l < Tk ? l : Tk; }

    if (t < Tq) {
        const float* qrow = Q + ((size_t)b * Tq + t) * HH + h * DHH;
        float4 q4[16];
#pragma unroll
        for (int kk = 0; kk < 16; kk++) q4[kk] = ((const float4*)qrow)[kk];

        float mx = -1e30f;
        for (int j = 0; j < limit; j++) {
            const float4* kr = (const float4*)(&Ks[j][0]);
            float s = 0.0f;
#pragma unroll
            for (int kk = 0; kk < 16; kk++) {
                float4 k4 = kr[kk];
                s += q4[kk].x * k4.x + q4[kk].y * k4.y + q4[kk].z * k4.z + q4[kk].w * k4.w;
            }
            s *= 0.125f;
            S[j][t] = s;
            mx = fmaxf(mx, s);
        }
        float den = 0.0f;
        for (int j = 0; j < limit; j++) {
            float e = expf(S[j][t] - mx);
            S[j][t] = e; den += e;
        }
        float inv = 1.0f / den;

        float4 acc4[16];
#pragma unroll
        for (int kk = 0; kk < 16; kk++) { acc4[kk].x = acc4[kk].y = acc4[kk].z = acc4[kk].w = 0.0f; }
        for (int j = 0; j < limit; j++) {
            float p = S[j][t];
            const float4* vr = (const float4*)(&Vs[j][0]);
#pragma unroll
            for (int kk = 0; kk < 16; kk++) {
                float4 v4 = vr[kk];
                acc4[kk].x += p * v4.x; acc4[kk].y += p * v4.y;
                acc4[kk].z += p * v4.z; acc4[kk].w += p * v4.w;
            }
        }
        __half* orow = O + ((size_t)b * Tq + t) * HH + h * DHH;
#pragma unroll
        for (int kk = 0; kk < 16; kk++) {
            __half2 h01 = __floats2half2_rn(acc4[kk].x * inv, acc4[kk].y * inv);
            __half2 h23 = __floats2half2_rn(acc4[kk].z * inv, acc4[kk].w * inv);
            ((__half2*)orow)[2*kk + 0] = h01;
            ((__half2*)orow)[2*kk + 1] = h23;
        }
    }
}

// ---------------------------------------------------------------------------
// Small helpers
// ---------------------------------------------------------------------------
__global__ void small_linear(const float* __restrict__ X, const float* __restrict__ W,
                             const float* __restrict__ bias, float* __restrict__ Y,
                             int M, int N, int K)
{
    int idx = blockIdx.x * blockDim.x + threadIdx.x;
    if (idx >= M * N) return;
    int m = idx / N, n = idx % N;
    const float* xr = X + (size_t)m * K;
    const float* wr = W + (size_t)n * K;
    float acc = bias[n];
    for (int k = 0; k < K; k++) acc += xr[k] * wr[k];
    Y[idx] = acc;
}

__global__ void bcast_kernel(const float* __restrict__ src, float* __restrict__ dst,
                             int per, size_t total)
{
    for (size_t i = blockIdx.x * (size_t)blockDim.x + threadIdx.x; i < total;
         i += (size_t)gridDim.x * blockDim.x)
        dst[i] = src[i % per];
}

__global__ void build_c2_kernel(const float* __restrict__ c, const float* __restrict__ dbp,
                                float* __restrict__ out)
{
    size_t total = (size_t)BB * NI_ * HH;
    for (size_t idx = blockIdx.x * (size_t)blockDim.x + threadIdx.x; idx < total;
         idx += (size_t)gridDim.x * blockDim.x) {
        size_t col = idx % HH;
        size_t r   = (idx / HH) % NI_;
        size_t b   = idx / ((size_t)NI_ * HH);
        out[idx] = (r < CC) ? c[(b * CC + r) * HH + col] : dbp[(r - CC) * HH + col];
    }
}

__global__ void score_softmax_kernel(const float* __restrict__ qg, const float* __restrict__ P,
                                     int N, const int* __restrict__ lens,
                                     float* __restrict__ mu)
{
    __shared__ float sc[64];
    int b = blockIdx.x, t = threadIdx.x;
    float val = -1e30f;
    if (t < N) {
        bool valid = (lens == nullptr) || (t < lens[b]);
        if (valid) {
            const float* qr = qg + (size_t)b * HH;
            const float* pr = P + ((size_t)b * N + t) * HH;
            float acc = 0.0f;
            for (int k = 0; k < HH; k++) acc += qr[k] * pr[k];
            val = acc * 0.04419417382415922f;
        }
    }
    sc[t] = val;
    __syncthreads();
    float mx = -1e30f;
    for (int j = 0; j < N; j++) mx = fmaxf(mx, sc[j]);
    float sum = 0.0f;
    for (int j = 0; j < N; j++) sum += expf(sc[j] - mx);
    int stride = N + DD;
    if (t < N) mu[(size_t)b * stride + t] = expf(sc[t] - mx) / sum;
    if (t < DD) mu[(size_t)b * stride + N + t] = 1.0f / DD;
}

__global__ void build_norm_kernel(const float* __restrict__ nf, int Tn,
                                  const float* __restrict__ dbp,
                                  float* __restrict__ out, int Tall)
{
    int warp = (blockIdx.x * blockDim.x + threadIdx.x) >> 5;
    int lane = threadIdx.x & 31;
    int rows = BB * Tall;
    if (warp >= rows) return;
    int b = warp / Tall, r = warp % Tall;
    const float* src = (r < Tn) ? nf + ((size_t)b * Tn + r) * HH : dbp + (size_t)(r - Tn) * HH;
    float v[16];
    float sq = 0.0f;
#pragma unroll
    for (int i = 0; i < 16; i++) { v[i] = src[i*32 + lane]; sq += v[i]*v[i]; }
#pragma unroll
    for (int o = 16; o > 0; o >>= 1) sq += __shfl_xor_sync(0xffffffffu, sq, o);
    float inv = 1.0f / fmaxf(sqrtf(sq), 1e-12f);
    float* dst = out + (size_t)warp * HH;
#pragma unroll
    for (int i = 0; i < 16; i++) dst[i*32 + lane] = v[i] * inv;
}

__global__ void sim_kernel(const float* __restrict__ Ai, const float* __restrict__ At,
                           float* __restrict__ sim)
{
    int b = blockIdx.x;
    const float4* ab = (const float4*)(Ai + (size_t)b * 40 * HH);
    const float4* tb = (const float4*)(At + (size_t)b * 68 * HH);
    for (int p = threadIdx.x; p < 40 * 68; p += blockDim.x) {
        int i = p / 68, j = p % 68;
        const float4* ar = ab + i * (HH/4);
        const float4* tr = tb + j * (HH/4);
        float acc = 0.0f;
        for (int k = 0; k < HH/4; k++) {
            float4 a = ar[k], t = tr[k];
            acc += a.x*t.x + a.y*t.y + a.z*t.z + a.w*t.w;
        }
        sim[((size_t)b * 40 + i) * 68 + j] = acc;
    }
}

__global__ __launch_bounds__(128)
void sinkhorn_kernel(const float* __restrict__ sim, const float* __restrict__ mu,
                     const float* __restrict__ mv, float* __restrict__ out)
{
    __shared__ float Km[40*68];
    __shared__ float Sm[40*68];
    __shared__ float u[40], v[68], muS[40], mvS[68], red[128];
    int b = blockIdx.x, t = threadIdx.x;

    for (int p = t; p < 40*68; p += 128) {
        float s = sim[(size_t)b * 40*68 + p];
        Sm[p] = s;
        Km[p] = expf((s - 1.0f) * 10.0f);
    }
    if (t < 40) muS[t] = mu[(size_t)b*40 + t];
    if (t < 68) { mvS[t] = mv[(size_t)b*68 + t]; v[t] = 1.0f; }
    __syncthreads();

    for (int it = 0; it < 10; it++) {
        if (t < 40) {
            float s = 0.0f;
            for (int j = 0; j < 68; j++) s += Km[t*68 + j] * v[j];
            u[t] = muS[t] / s;
        }
        __syncthreads();
        if (t < 68) {
            float s = 0.0f;
            for (int i = 0; i < 40; i++) s += Km[i*68 + t] * u[i];
            v[t] = mvS[t] / s;
        }
        __syncthreads();
    }

    float acc = 0.0f;
    for (int p = t; p < NI_*NT_; p += 128) {
        int i = p / NT_, j = p % NT_;
        float k = Km[i*68 + j];
        acc += u[i] * k * v[j] * Sm[i*68 + j];
    }
    red[t] = acc;
    __syncthreads();
    for (int o = 64; o > 0; o >>= 1) {
        if (t < o) red[t] += red[t + o];
        __syncthreads();
    }
    if (t == 0) out[b] = red[0];
}

// ---------------------------------------------------------------------------
// Host-side helpers
// ---------------------------------------------------------------------------
static inline void gemm(cudaStream_t st, int epi, int wh, const __half* A,
                        const __half* W,
                        const float* bias, const float* res, float* C, __half* Ch,
                        int M, int N, int K)
{
    dim3 grid(N / 128, M / 128);
    if (epi == 0 && wh == 1)
        hgemm_kernel<0,1><<<grid, 256, HSMEM, st>>>(A, W, bias, res, C, Ch, M, N, K);
    else if (epi == 0 && wh == 3)
        hgemm_kernel<0,3><<<grid, 256, HSMEM, st>>>(A, W, bias, res, C, Ch, M, N, K);
    else if (epi == 1)
        hgemm_kernel<1,1><<<grid, 256, HSMEM, st>>>(A, W, bias, res, C, Ch, M, N, K);
    else
        hgemm_kernel<2,2><<<grid, 256, HSMEM, st>>>(A, W, bias, res, C, Ch, M, N, K);
}

static inline void ln_run(cudaStream_t st, const float* x, float* yf, __half* yh,
                          const float* g, const float* b, int rows)
{
    int blocks = (rows + 7) / 8;
    ln_kernel<<<blocks, 256, 0, st>>>(x, yf, yh, g, b, rows);
}

struct Params {
    const float *attn_in_b, *attn_out_b, *ff1_b, *ff2_b, *lln_g, *lln_b;
    const int* lengths;
    float* base;
    __half* hb;
    __half* wb;
};

static void xlayer(const Params& P, cudaStream_t st, int lane,
                   const float* src, int Ts, float* tgt, int Tt,
                   int s, int l, bool masked)
{
    float* base = P.base;
    __half* hl = P.hb + HB_LANE + (size_t)lane * LANE_H;
    __half* wb = P.wb;
    __half* h_tgtln = hl + HL_TGT;
    __half* h_srcln = hl + HL_SRC;
    __half* h_ao    = hl + HL_AO;
    __half* h_hid   = hl + HL_HID;
    float* p_q  = base + O_LANEF + (size_t)lane * LANE_F + OL_Q;
    float* p_kv = base + O_LANEF + (size_t)lane * LANE_F + OL_KV;

    const int Mt = BB * Tt, Ms = BB * Ts;
    const int sl = s * LL + l;
    const float* lg = P.lln_g + (size_t)sl * 3 * HH;
    const float* lb = P.lln_b + (size_t)sl * 3 * HH;
    const float* ib = P.attn_in_b  + (size_t)sl * 3 * HH;
    const float* ob = P.attn_out_b + (size_t)sl * HH;
    const float* f1b = P.ff1_b + (size_t)sl * 4 * HH;
    const float* f2b = P.ff2_b + (size_t)sl * HH;

    __half* ain  = wb + WO_AIN  + (size_t)sl * 3 * HH * HH;
    __half* aout = wb + WO_AOUT + (size_t)sl * HH * HH;
    __half* f1   = wb + WO_FF1  + (size_t)sl * 4 * HH * HH;
    __half* f2   = wb + WO_FF2  + (size_t)sl * 4 * HH * HH;

    ln_run(st, src, nullptr, h_srcln, lg + 0*HH, lb + 0*HH, Ms);
    ln_run(st, tgt, nullptr, h_tgtln, lg + 1*HH, lb + 1*HH, Mt);
    gemm(st, 0, 1, h_tgtln, ain, ib, nullptr, p_q, nullptr, Mt, HH, HH);
    gemm(st, 0, 1, h_srcln, ain + (size_t)HH*HH, ib + HH,
         nullptr, p_kv, nullptr, Ms, 2*HH, HH);
    attn_kernel<<<BB * NHH, 64, 0, st>>>(p_q, p_kv, h_ao, Tt, Ts,
                                         masked ? P.lengths : nullptr);
    gemm(st, 1, 1, h_ao, aout, ob, tgt, tgt, nullptr, Mt, HH, HH);
    ln_run(st, tgt, nullptr, h_tgtln, lg + 2*HH, lb + 2*HH, Mt);
    gemm(st, 2, 2, h_tgtln, f1, f1b, nullptr, nullptr, h_hid, Mt, 4*HH, HH);
    gemm(st, 1, 1, h_hid, f2, f2b, tgt, tgt, nullptr, Mt, HH, 4*HH);
}

// ---------------------------------------------------------------------------
// kernel_launch
// ---------------------------------------------------------------------------
extern "C" void kernel_launch(void* const* d_in, const int* in_sizes, int n_in,
                              void* d_out, int out_size)
{
    const float* img_global   = (const float*)d_in[0];
    const float* img_nodes    = (const float*)d_in[1];
    const float* txt_global   = (const float*)d_in[2];
    const float* txt_nodes    = (const float*)d_in[3];
    const int*   lengths      = (const int*)  d_in[4];
    const float* img_in_w     = (const float*)d_in[5];
    const float* img_in_b     = (const float*)d_in[6];
    const float* txt_in_w     = (const float*)d_in[7];
    const float* txt_in_b     = (const float*)d_in[8];
    const float* img_concepts = (const float*)d_in[9];
    const float* txt_concepts = (const float*)d_in[10];
    const float* img_dustbins = (const float*)d_in[11];
    const float* txt_dustbins = (const float*)d_in[12];
    const float* ln_g         = (const float*)d_in[13];
    const float* ln_b         = (const float*)d_in[14];
    const float* attn_in_w    = (const float*)d_in[15];
    const float* attn_in_b    = (const float*)d_in[16];
    const float* attn_out_w   = (const float*)d_in[17];
    const float* attn_out_b   = (const float*)d_in[18];
    const float* ff1_w        = (const float*)d_in[19];
    const float* ff1_b        = (const float*)d_in[20];
    const float* ff2_w        = (const float*)d_in[21];
    const float* ff2_b        = (const float*)d_in[22];
    const float* lln_g        = (const float*)d_in[23];
    const float* lln_b        = (const float*)d_in[24];
    const float* db_w         = (const float*)d_in[25];
    const float* db_b         = (const float*)d_in[26];
    const float* proj_w       = (const float*)d_in[27];
    const float* proj_b       = (const float*)d_in[28];
    const float* qg_w         = (const float*)d_in[29];
    const float* qg_b         = (const float*)d_in[30];
    float* out = (float*)d_out;

    cudaFuncSetAttribute(hgemm_kernel<0,1>, cudaFuncAttributeMaxDynamicSharedMemorySize, HSMEM);
    cudaFuncSetAttribute(hgemm_kernel<0,3>, cudaFuncAttributeMaxDynamicSharedMemorySize, HSMEM);
    cudaFuncSetAttribute(hgemm_kernel<1,1>, cudaFuncAttributeMaxDynamicSharedMemorySize, HSMEM);
    cudaFuncSetAttribute(hgemm_kernel<2,2>, cudaFuncAttributeMaxDynamicSharedMemorySize, HSMEM);

    float* base = nullptr;
    cudaGetSymbolAddress((void**)&base, g_buf);
    __half* hb = nullptr;
    cudaGetSymbolAddress((void**)&hb, g_hbuf);
    __half* wb = nullptr;
    cudaGetSymbolAddress((void**)&wb, g_wbuf);

    // --- streams & events (created per call; host handles intentionally leaked:
    // kernel_launch runs only for correctness + capture, never per-replay) ---
    cudaStream_t sA = 0;            // legacy default stream (the captured one)
    cudaStream_t sB;
    cudaStreamCreateWithFlags(&sB, cudaStreamNonBlocking);
    cudaEvent_t evs[64];
    for (int i = 0; i < 64; i++) cudaEventCreateWithFlags(&evs[i], cudaEventDisableTiming);
    int evi = 0;
    auto forkto = [&](cudaStream_t to, cudaStream_t from) {
        cudaEventRecord(evs[evi], from);
        cudaStreamWaitEvent(to, evs[evi], 0);
        evi++;
    };
    auto joinAB = [&]() { forkto(sB, sA); forkto(sA, sB); };

    float* p_imgn  = base + O_IMGN;
    float* p_txtn  = base + O_TXTN;
    float* p_imgc  = base + O_IMGC;
    float* p_txtc  = base + O_TXTC;
    float* p_c2a   = base + O_C2A;
    float* p_c2b   = base + O_C2B;
    float* p_imgnf = base + O_IMGNF;
    float* p_txtnf = base + O_TXTNF;
    float* p_p2    = base + O_P2;
    float* p_p3    = base + O_P3;
    float* p_qi    = base + O_QI;
    float* p_qt    = base + O_QT;
    float* p_alli  = base + O_ALLI;
    float* p_allt  = base + O_ALLT;
    float* p_sim   = base + O_SIM;
    float* p_mu    = base + O_MU;
    float* p_mv    = base + O_MV;
    float* p_cn0   = base + O_CN0;
    float* p_cn1   = base + O_CN1;
    float* p_db0   = base + O_DB0;
    float* p_db1   = base + O_DB1;
    float* p_dbp   = base + O_DBP;
    float* p_dbp2  = base + O_DBP2;
    float* p_tmpA  = base + O_LANEF + OL_Q;             // lane0 Q as fp32 tmp
    float* p_tmpB  = base + O_LANEF + LANE_F + OL_Q;    // lane1 Q as fp32 tmp
    __half* hl0 = hb + HB_LANE;
    __half* hl1 = hb + HB_LANE + LANE_H;

    // fork B off the origin before any B work
    forkto(sB, sA);

    // --- weight/input conversion, split across streams ---
    wconv_kernel<<<1024, 256, 0, sA>>>(img_in_w,   wb + WO_IMGIN, SZ_IMGIN/4);
    wconv_kernel<<<2048, 256, 0, sA>>>(attn_in_w,  wb + WO_AIN,   SZ_AIN/4);
    wconv_kernel<<<2048, 256, 0, sA>>>(ff1_w,      wb + WO_FF1,   SZ_FF1/4);
    wconv_kernel<<<1024, 256, 0, sA>>>(proj_w,     wb + WO_PROJ,  SZ_PROJ/4);
    aconv_kernel<<<2048, 256, 0, sA>>>(img_nodes,  hb + HB_INI, (size_t)BB*NI_*DI_/4);
    aconv_kernel<<<512,  256, 0, sA>>>(img_global, hb + HB_GI,  (size_t)BB*GG/4);
    ln_run(sA, img_concepts, p_cn0, nullptr, ln_g + 4*HH, ln_b + 4*HH, CC);
    ln_run(sA, img_dustbins, p_db0, nullptr, ln_g + 6*HH, ln_b + 6*HH, DD);
    bcast_kernel<<<2048, 256, 0, sA>>>(p_cn0, p_imgc, CC*HH, (size_t)BB*CC*HH);

    wconv_kernel<<<1024, 256, 0, sB>>>(txt_in_w,   wb + WO_TXTIN, SZ_TXTIN/4);
    wconv_kernel<<<1024, 256, 0, sB>>>(attn_out_w, wb + WO_AOUT,  SZ_AOUT/4);
    wconv_kernel<<<2048, 256, 0, sB>>>(ff2_w,      wb + WO_FF2,   SZ_FF2/4);
    wconv_kernel<<<1024, 256, 0, sB>>>(qg_w,       wb + WO_QG,    SZ_QG/4);
    aconv_kernel<<<2048, 256, 0, sB>>>(txt_nodes,  hb + HB_INT, (size_t)BB*NT_*DT_/4);
    aconv_kernel<<<512,  256, 0, sB>>>(txt_global, hb + HB_GT,  (size_t)BB*GG/4);
    ln_run(sB, txt_concepts, p_cn1, nullptr, ln_g + 5*HH, ln_b + 5*HH, CC);
    ln_run(sB, txt_dustbins, p_db1, nullptr, ln_g + 7*HH, ln_b + 7*HH, DD);
    bcast_kernel<<<2048, 256, 0, sB>>>(p_cn1, p_txtc, CC*HH, (size_t)BB*CC*HH);

    // --- input projections + LN (A: img, B: txt) ---
    gemm(sA, 0, 1, hb + HB_INI, wb + WO_IMGIN, img_in_b,
         nullptr, p_tmpA, nullptr, BB*NI_, HH, DI_);
    ln_run(sA, p_tmpA, p_imgn, nullptr, ln_g + 0*HH, ln_b + 0*HH, BB*NI_);
    gemm(sB, 0, 1, hb + HB_INT, wb + WO_TXTIN, txt_in_b,
         nullptr, p_tmpB, nullptr, BB*NT_, HH, DT_);
    ln_run(sB, p_tmpB, p_txtn, nullptr, ln_g + 1*HH, ln_b + 1*HH, BB*NT_);

    Params P{attn_in_b, attn_out_b, ff1_b, ff2_b, lln_g, lln_b, lengths, base, hb, wb};

    // --- layers (A: img-side, B: txt-side; joins at true dependency points) ---
    for (int l = 0; l < LL; l++) {
        joinAB();
        xlayer(P, sA, 0, p_imgn, NI_, p_imgc, CC, 0, l, false);
        small_linear<<<(DD*HH + 255)/256, 256, 0, sA>>>(p_db0, db_w + (size_t)(0*LL + l)*HH*HH,
                                                        db_b + (size_t)(0*LL + l)*HH, p_dbp, DD, HH, HH);
        build_c2_kernel<<<4096, 256, 0, sA>>>(p_imgc, p_dbp, p_c2a);

        xlayer(P, sB, 1, p_txtn, NT_, p_txtc, CC, 1, l, true);
        small_linear<<<(DD*HH + 255)/256, 256, 0, sB>>>(p_db1, db_w + (size_t)(1*LL + l)*HH*HH,
                                                        db_b + (size_t)(1*LL + l)*HH, p_dbp2, DD, HH, HH);
        build_c2_kernel<<<4096, 256, 0, sB>>>(p_txtc, p_dbp2, p_c2b);

        joinAB();
        xlayer(P, sA, 0, p_c2a, NI_, p_txtn, NT_, 2, l, false);
        xlayer(P, sB, 1, p_c2b, NI_, p_imgn, NI_, 3, l, false);
    }
    joinAB();

    // --- tail (A: img-side, B: txt-side) ---
    __half* proj = wb + WO_PROJ;

    ln_run(sA, p_imgn, nullptr, hl0 + HL_SRC, ln_g + 2*HH, ln_b + 2*HH, BB*NI_);
    gemm(sA, 0, 3, hl0 + HL_SRC, proj, proj_b, nullptr,
         p_imgnf, hb + HB_IMGNF, BB*NI_, HH, HH);
    gemm(sA, 0, 1, hb + HB_IMGNF, proj + 2*(size_t)HH*HH,
         proj_b + 2*HH, nullptr, p_p2, nullptr, BB*NI_, HH, HH);
    gemm(sA, 0, 1, hb + HB_GI, wb + WO_QG, qg_b,
         nullptr, p_qi, nullptr, BB, HH, GG);
    score_softmax_kernel<<<BB, 64, 0, sA>>>(p_qi, p_p2, NI_, nullptr, p_mu);
    small_linear<<<(DD*HH + 255)/256, 256, 0, sA>>>(p_db0, proj_w + 4*(size_t)HH*HH,
                                                    proj_b + 4*HH, p_dbp, DD, HH, HH);
    build_norm_kernel<<<(BB*40*32 + 255)/256, 256, 0, sA>>>(p_imgnf, NI_, p_dbp, p_alli, 40);

    ln_run(sB, p_txtn, nullptr, hl1 + HL_SRC, ln_g + 3*HH, ln_b + 3*HH, BB*NT_);
    gemm(sB, 0, 3, hl1 + HL_SRC, proj + (size_t)HH*HH,
         proj_b + HH, nullptr, p_txtnf, hb + HB_TXTNF, BB*NT_, HH, HH);
    gemm(sB, 0, 1, hb + HB_TXTNF, proj + 3*(size_t)HH*HH,
         proj_b + 3*HH, nullptr, p_p3, nullptr, BB*NT_, HH, HH);
    gemm(sB, 0, 1, hb + HB_GT, wb + WO_QG + (size_t)HH*GG,
         qg_b + HH, nullptr, p_qt, nullptr, BB, HH, GG);
    score_softmax_kernel<<<BB, 64, 0, sB>>>(p_qt, p_p3, NT_, lengths, p_mv);
    small_linear<<<(DD*HH + 255)/256, 256, 0, sB>>>(p_db1, proj_w + 5*(size_t)HH*HH,
                                                    proj_b + 5*HH, p_dbp2, DD, HH, HH);
    build_norm_kernel<<<(BB*68*32 + 255)/256, 256, 0, sB>>>(p_txtnf, NT_, p_dbp2, p_allt, 68);

    // join B back into origin, finish on A
    forkto(sA, sB);
    sim_kernel<<<BB, 256, 0, sA>>>(p_alli, p_allt, p_sim);
    sinkhorn_kernel<<<BB, 128, 0, sA>>>(p_sim, p_mu, p_mv, out);
}